// round 3
// baseline (speedup 1.0000x reference)
#include <cuda_runtime.h>

#define BN 2
#define LN 12288
#define KN 32
#define IN 768
#define CT 128
#define CA 16
#define RMS_EPS 1e-6f

typedef unsigned long long u64;

// Scratch (allocs are banned; device globals are the sanctioned workaround)
__device__ float g_Sl[BN * LN * CA];                  // 1.5 MB
__device__ float g_Sm[BN * LN * CA];                  // 1.5 MB
__device__ float g_Zp[(size_t)IN * IN * CA];          // 37.75 MB

// ---- packed f32x2 helpers (sm_100+) ---------------------------------------
__device__ __forceinline__ u64 pack2(float a, float b) {
    u64 v;
    asm("mov.b64 %0, {%1, %2};" : "=l"(v) : "r"(__float_as_uint(a)), "r"(__float_as_uint(b)));
    return v;
}
__device__ __forceinline__ void unpack2(u64 v, float& a, float& b) {
    unsigned x, y;
    asm("mov.b64 {%0, %1}, %2;" : "=r"(x), "=r"(y) : "l"(v));
    a = __uint_as_float(x); b = __uint_as_float(y);
}
__device__ __forceinline__ void fma2(u64& d, u64 a, u64 b) {
    asm("fma.rn.f32x2 %0, %1, %2, %0;" : "+l"(d) : "l"(a), "l"(b));
}

// ---------------------------------------------------------------------------
// Kernel 1: S_l / S_m projections. Thread-per-row, reduction dim paired for
// f32x2. 64-thread blocks so the 24576 rows spread over all 148 SMs.
// ---------------------------------------------------------------------------
__global__ void __launch_bounds__(64) sproj_kernel(
    const float* __restrict__ CL,
    const float* __restrict__ Wl,
    const float* __restrict__ Wm)
{
    // sW?2[t2*8 + c2] = { pack(W[2t2][2c2],   W[2t2+1][2c2]),
    //                     pack(W[2t2][2c2+1], W[2t2+1][2c2+1]) }
    __shared__ ulonglong2 sWl2[512];
    __shared__ ulonglong2 sWm2[512];
    for (int i = threadIdx.x; i < 512; i += 64) {
        int t2 = i >> 3, c2 = i & 7;
        int t0 = 2 * t2, t1 = t0 + 1, c0 = 2 * c2, c1 = c0 + 1;
        sWl2[i] = make_ulonglong2(pack2(Wl[t0 * CA + c0], Wl[t1 * CA + c0]),
                                  pack2(Wl[t0 * CA + c1], Wl[t1 * CA + c1]));
        sWm2[i] = make_ulonglong2(pack2(Wm[t0 * CA + c0], Wm[t1 * CA + c0]),
                                  pack2(Wm[t0 * CA + c1], Wm[t1 * CA + c1]));
    }
    __syncthreads();

    int row = blockIdx.x * 64 + threadIdx.x;
    if (row >= BN * LN) return;

    const float4* xr = reinterpret_cast<const float4*>(CL + (size_t)row * CT);

    u64 al2[CA], am2[CA];
#pragma unroll
    for (int c = 0; c < CA; c++) { al2[c] = 0ull; am2[c] = 0ull; }

#pragma unroll 1
    for (int i = 0; i < CT / 4; i++) {
        float4 v = __ldg(xr + i);
        u64 p01 = pack2(fmaxf(v.x, 0.f), fmaxf(v.y, 0.f));
        u64 p23 = pack2(fmaxf(v.z, 0.f), fmaxf(v.w, 0.f));
        const ulonglong2* wla = sWl2 + (2 * i) * 8;
        const ulonglong2* wlb = sWl2 + (2 * i + 1) * 8;
        const ulonglong2* wma = sWm2 + (2 * i) * 8;
        const ulonglong2* wmb = sWm2 + (2 * i + 1) * 8;
#pragma unroll
        for (int c2 = 0; c2 < 8; c2++) {
            ulonglong2 w = wla[c2];
            fma2(al2[2 * c2], p01, w.x);
            fma2(al2[2 * c2 + 1], p01, w.y);
        }
#pragma unroll
        for (int c2 = 0; c2 < 8; c2++) {
            ulonglong2 w = wlb[c2];
            fma2(al2[2 * c2], p23, w.x);
            fma2(al2[2 * c2 + 1], p23, w.y);
        }
#pragma unroll
        for (int c2 = 0; c2 < 8; c2++) {
            ulonglong2 w = wma[c2];
            fma2(am2[2 * c2], p01, w.x);
            fma2(am2[2 * c2 + 1], p01, w.y);
        }
#pragma unroll
        for (int c2 = 0; c2 < 8; c2++) {
            ulonglong2 w = wmb[c2];
            fma2(am2[2 * c2], p23, w.x);
            fma2(am2[2 * c2 + 1], p23, w.y);
        }
    }

    float* ol = g_Sl + (size_t)row * CA;
    float* om = g_Sm + (size_t)row * CA;
#pragma unroll
    for (int c2 = 0; c2 < 4; c2++) {
        float a0, a1, b0, b1, c0f, c1f, d0, d1;
        unpack2(al2[4 * c2 + 0], a0, a1);
        unpack2(al2[4 * c2 + 1], b0, b1);
        unpack2(al2[4 * c2 + 2], c0f, c1f);
        unpack2(al2[4 * c2 + 3], d0, d1);
        reinterpret_cast<float4*>(ol)[c2] = make_float4(a0 + a1, b0 + b1, c0f + c1f, d0 + d1);
        unpack2(am2[4 * c2 + 0], a0, a1);
        unpack2(am2[4 * c2 + 1], b0, b1);
        unpack2(am2[4 * c2 + 2], c0f, c1f);
        unpack2(am2[4 * c2 + 3], d0, d1);
        reinterpret_cast<float4*>(om)[c2] = make_float4(a0 + a1, b0 + b1, c0f + c1f, d0 + d1);
    }
}

// ---------------------------------------------------------------------------
// Kernel 2: Z_proc = rmsnorm(Z) * rms_w @ W_z, rms_w folded into W.
// Thread-per-row, f32x2 packed over the reduction dim.
// ---------------------------------------------------------------------------
__global__ void __launch_bounds__(256) zproc_kernel(
    const float* __restrict__ Z,
    const float* __restrict__ rmsw,
    const float* __restrict__ Wz)
{
    __shared__ ulonglong2 sW2[512];
    for (int i = threadIdx.x; i < 512; i += 256) {
        int t2 = i >> 3, c2 = i & 7;
        int t0 = 2 * t2, t1 = t0 + 1, c0 = 2 * c2, c1 = c0 + 1;
        float r0 = rmsw[t0], r1 = rmsw[t1];
        sW2[i] = make_ulonglong2(pack2(r0 * Wz[t0 * CA + c0], r1 * Wz[t1 * CA + c0]),
                                 pack2(r0 * Wz[t0 * CA + c1], r1 * Wz[t1 * CA + c1]));
    }
    __syncthreads();

    int row = blockIdx.x * blockDim.x + threadIdx.x;
    if (row >= IN * IN) return;

    const float4* zr = reinterpret_cast<const float4*>(Z + (size_t)row * CT);

    u64 acc2[CA];
#pragma unroll
    for (int c = 0; c < CA; c++) acc2[c] = 0ull;
    u64 ss2 = 0ull;

#pragma unroll 2
    for (int i = 0; i < CT / 4; i++) {
        float4 v = __ldg(zr + i);
        u64 p01 = pack2(v.x, v.y);
        u64 p23 = pack2(v.z, v.w);
        fma2(ss2, p01, p01);
        fma2(ss2, p23, p23);
        const ulonglong2* wa = sW2 + (2 * i) * 8;
        const ulonglong2* wb = sW2 + (2 * i + 1) * 8;
#pragma unroll
        for (int c2 = 0; c2 < 8; c2++) {
            ulonglong2 w = wa[c2];
            fma2(acc2[2 * c2], p01, w.x);
            fma2(acc2[2 * c2 + 1], p01, w.y);
        }
#pragma unroll
        for (int c2 = 0; c2 < 8; c2++) {
            ulonglong2 w = wb[c2];
            fma2(acc2[2 * c2], p23, w.x);
            fma2(acc2[2 * c2 + 1], p23, w.y);
        }
    }

    float sa, sb;
    unpack2(ss2, sa, sb);
    float scale = rsqrtf((sa + sb) * (1.0f / CT) + RMS_EPS);

    float* o = g_Zp + (size_t)row * CA;
#pragma unroll
    for (int c2 = 0; c2 < 4; c2++) {
        float a0, a1, b0, b1, c0f, c1f, d0, d1;
        unpack2(acc2[4 * c2 + 0], a0, a1);
        unpack2(acc2[4 * c2 + 1], b0, b1);
        unpack2(acc2[4 * c2 + 2], c0f, c1f);
        unpack2(acc2[4 * c2 + 3], d0, d1);
        reinterpret_cast<float4*>(o)[c2] =
            make_float4((a0 + a1) * scale, (b0 + b1) * scale,
                        (c0f + c1f) * scale, (d0 + d1) * scale);
    }
}

// ---------------------------------------------------------------------------
// Kernel 3: pair assembly + residual MLP (f32x2 packed MLP).
// ---------------------------------------------------------------------------
__device__ __forceinline__ void mlp_layer2(const float* in, const ulonglong2* W2, float* out)
{
    u64 acc2[CA];
#pragma unroll
    for (int c = 0; c < CA; c++) acc2[c] = 0ull;
#pragma unroll
    for (int j2 = 0; j2 < 8; j2++) {
        u64 rr = pack2(fmaxf(in[2 * j2], 0.f), fmaxf(in[2 * j2 + 1], 0.f));
#pragma unroll
        for (int c2 = 0; c2 < 8; c2++) {
            ulonglong2 w = W2[j2 * 8 + c2];
            fma2(acc2[2 * c2], rr, w.x);
            fma2(acc2[2 * c2 + 1], rr, w.y);
        }
    }
#pragma unroll
    for (int c = 0; c < CA; c++) {
        float a, b;
        unpack2(acc2[c], a, b);
        out[c] = a + b;
    }
}

__global__ void __launch_bounds__(128) pair_kernel(
    const float* __restrict__ motif_pos,
    const float* __restrict__ is_motif_coord,   // bool serialized as float32
    const float* __restrict__ ref_pos,
    const int* __restrict__ ref_space_uid,
    const float* __restrict__ is_motif_seq,     // bool serialized as float32
    const int* __restrict__ indices,
    const int* __restrict__ tok_idx,
    const float* __restrict__ Wd_m, const float* __restrict__ Wi_m, const float* __restrict__ Wk_m,
    const float* __restrict__ Wd_r, const float* __restrict__ Wi_r, const float* __restrict__ Wk_r,
    const float* __restrict__ W1, const float* __restrict__ W2, const float* __restrict__ W3,
    float* __restrict__ out)
{
    __shared__ float sWd_m[3 * CA], sWi_m[CA], sWk_m[CA];
    __shared__ float sWd_r[3 * CA], sWi_r[CA], sWk_r[CA];
    __shared__ ulonglong2 sW1_2[64], sW2_2[64], sW3_2[64];

    int t = threadIdx.x;
    for (int i = t; i < 3 * CA; i += 128) { sWd_m[i] = Wd_m[i]; sWd_r[i] = Wd_r[i]; }
    for (int i = t; i < CA; i += 128) {
        sWi_m[i] = Wi_m[i]; sWk_m[i] = Wk_m[i];
        sWi_r[i] = Wi_r[i]; sWk_r[i] = Wk_r[i];
    }
    for (int i = t; i < 64; i += 128) {
        int j2 = i >> 3, c2 = i & 7;
        int j0 = 2 * j2, j1 = j0 + 1, c0 = 2 * c2, c1 = c0 + 1;
        sW1_2[i] = make_ulonglong2(pack2(W1[j0 * CA + c0], W1[j1 * CA + c0]),
                                   pack2(W1[j0 * CA + c1], W1[j1 * CA + c1]));
        sW2_2[i] = make_ulonglong2(pack2(W2[j0 * CA + c0], W2[j1 * CA + c0]),
                                   pack2(W2[j0 * CA + c1], W2[j1 * CA + c1]));
        sW3_2[i] = make_ulonglong2(pack2(W3[j0 * CA + c0], W3[j1 * CA + c0]),
                                   pack2(W3[j0 * CA + c1], W3[j1 * CA + c1]));
    }
    __syncthreads();

    int q = blockIdx.x * 4 + (t >> 5);   // query index in [0, B*L)
    if (q >= BN * LN) return;
    int lane = t & 31;                   // k
    int b = q / LN;
    int l = q - b * LN;

    int idx = indices[(size_t)q * KN + lane];
    idx = min(max(idx, 0), LN - 1);

    // issue the long-latency index gather early
    int tk_raw = __ldg(tok_idx + idx);
    int tq_raw = __ldg(tok_idx + l);

    float P[CA];

    // S_l (query, warp-uniform) + S_m gather (key)
    {
        const float4* slp = reinterpret_cast<const float4*>(g_Sl + (size_t)q * CA);
        const float4* smp = reinterpret_cast<const float4*>(g_Sm + ((size_t)b * LN + idx) * CA);
#pragma unroll
        for (int cc = 0; cc < 4; cc++) {
            float4 a = __ldg(slp + cc);
            float4 m = __ldg(smp + cc);
            P[cc * 4 + 0] = a.x + m.x;
            P[cc * 4 + 1] = a.y + m.y;
            P[cc * 4 + 2] = a.z + m.z;
            P[cc * 4 + 3] = a.w + m.w;
        }
    }

    // token-pair Z gather
    {
        int tq = min(max(tq_raw, 0), IN - 1);
        int tk = min(max(tk_raw, 0), IN - 1);
        const float4* zp = reinterpret_cast<const float4*>(g_Zp + ((size_t)tq * IN + tk) * CA);
#pragma unroll
        for (int cc = 0; cc < 4; cc++) {
            float4 z = __ldg(zp + cc);
            P[cc * 4 + 0] += z.x;
            P[cc * 4 + 1] += z.y;
            P[cc * 4 + 2] += z.z;
            P[cc * 4 + 3] += z.w;
        }
    }

    // motif-position branch: query mask AND key mask (0/1 masks)
    if (is_motif_coord[l] != 0.f && is_motif_coord[idx] != 0.f) {
        float dx = motif_pos[l * 3 + 0] - motif_pos[idx * 3 + 0];
        float dy = motif_pos[l * 3 + 1] - motif_pos[idx * 3 + 1];
        float dz = motif_pos[l * 3 + 2] - motif_pos[idx * 3 + 2];
        float inv = 1.0f / (1.0f + dx * dx + dy * dy + dz * dz);
#pragma unroll
        for (int c = 0; c < CA; c++)
            P[c] += dx * sWd_m[c] + dy * sWd_m[CA + c] + dz * sWd_m[2 * CA + c]
                  + inv * sWi_m[c] + sWk_m[c];
    }

    // ref-position branch: query is_motif_seq AND (same uid AND key is_motif_seq)
    if (is_motif_seq[l] != 0.f) {
        if (ref_space_uid[idx] == ref_space_uid[l] && is_motif_seq[idx] != 0.f) {
            float dx = ref_pos[l * 3 + 0] - ref_pos[idx * 3 + 0];
            float dy = ref_pos[l * 3 + 1] - ref_pos[idx * 3 + 1];
            float dz = ref_pos[l * 3 + 2] - ref_pos[idx * 3 + 2];
            float inv = 1.0f / (1.0f + dx * dx + dy * dy + dz * dz);
#pragma unroll
            for (int c = 0; c < CA; c++)
                P[c] += dx * sWd_r[c] + dy * sWd_r[CA + c] + dz * sWd_r[2 * CA + c]
                      + inv * sWi_r[c] + sWk_r[c];
        }
    }

    // residual MLP: h = relu->W1 -> relu->W2 -> relu->W3 ; out = P + h
    float h0[CA], h1[CA];
    mlp_layer2(P,  sW1_2, h0);
    mlp_layer2(h0, sW2_2, h1);
    mlp_layer2(h1, sW3_2, h0);

    float4* op = reinterpret_cast<float4*>(out + ((size_t)q * KN + lane) * CA);
#pragma unroll
    for (int cc = 0; cc < 4; cc++)
        op[cc] = make_float4(P[cc * 4 + 0] + h0[cc * 4 + 0],
                             P[cc * 4 + 1] + h0[cc * 4 + 1],
                             P[cc * 4 + 2] + h0[cc * 4 + 2],
                             P[cc * 4 + 3] + h0[cc * 4 + 3]);
}

// ---------------------------------------------------------------------------
extern "C" void kernel_launch(void* const* d_in, const int* in_sizes, int n_in,
                              void* d_out, int out_size)
{
    const float* motif_pos      = (const float*)d_in[0];
    const float* is_motif_coord = (const float*)d_in[1];
    const float* ref_pos        = (const float*)d_in[2];
    const int*   ref_space_uid  = (const int*)d_in[3];
    const float* is_motif_seq   = (const float*)d_in[4];
    const int*   indices        = (const int*)d_in[5];
    const float* C_L            = (const float*)d_in[6];
    const float* Z              = (const float*)d_in[7];
    const int*   tok_idx        = (const int*)d_in[8];
    const float* W_d_m          = (const float*)d_in[9];
    const float* W_inv_m        = (const float*)d_in[10];
    const float* W_mask_m       = (const float*)d_in[11];
    const float* W_d_r          = (const float*)d_in[12];
    const float* W_inv_r        = (const float*)d_in[13];
    const float* W_mask_r       = (const float*)d_in[14];
    const float* W_single_l     = (const float*)d_in[15];
    const float* W_single_m     = (const float*)d_in[16];
    const float* rms_w          = (const float*)d_in[17];
    const float* W_z            = (const float*)d_in[18];
    const float* W_mlp1         = (const float*)d_in[19];
    const float* W_mlp2         = (const float*)d_in[20];
    const float* W_mlp3         = (const float*)d_in[21];
    float* out = (float*)d_out;

    sproj_kernel<<<(BN * LN + 63) / 64, 64>>>(C_L, W_single_l, W_single_m);
    zproc_kernel<<<(IN * IN + 255) / 256, 256>>>(Z, rms_w, W_z);
    pair_kernel<<<(BN * LN + 3) / 4, 128>>>(
        motif_pos, is_motif_coord, ref_pos, ref_space_uid, is_motif_seq,
        indices, tok_idx,
        W_d_m, W_inv_m, W_mask_m, W_d_r, W_inv_r, W_mask_r,
        W_mlp1, W_mlp2, W_mlp3, out);
}

// round 4
// speedup vs baseline: 1.0863x; 1.0863x over previous
#include <cuda_runtime.h>

#define BN 2
#define LN 12288
#define KN 32
#define IN 768
#define CT 128
#define CA 16
#define RMS_EPS 1e-6f

typedef unsigned long long u64;

// Scratch (allocs are banned; device globals are the sanctioned workaround)
__device__ float g_Sl[BN * LN * CA];                  // 1.5 MB
__device__ float g_Sm[BN * LN * CA];                  // 1.5 MB
__device__ float g_Zp[(size_t)IN * IN * CA];          // 37.75 MB

// ---- packed f32x2 helpers (sm_100+) ---------------------------------------
__device__ __forceinline__ u64 pack2(float a, float b) {
    u64 v;
    asm("mov.b64 %0, {%1, %2};" : "=l"(v) : "r"(__float_as_uint(a)), "r"(__float_as_uint(b)));
    return v;
}
__device__ __forceinline__ void unpack2(u64 v, float& a, float& b) {
    unsigned x, y;
    asm("mov.b64 {%0, %1}, %2;" : "=r"(x), "=r"(y) : "l"(v));
    a = __uint_as_float(x); b = __uint_as_float(y);
}
__device__ __forceinline__ void fma2(u64& d, u64 a, u64 b) {
    asm("fma.rn.f32x2 %0, %1, %2, %0;" : "+l"(d) : "l"(a), "l"(b));
}

// ---------------------------------------------------------------------------
// Kernel 2 (launched FIRST for ncu): Z_proc = rmsnorm(Z)*rms_w @ W_z.
// 64 rows per 64-thread block. Rows staged coalesced into smem with a
// 132-word row pitch (132 mod 32 = 4 -> conflict-free LDS.128 per phase).
// ---------------------------------------------------------------------------
#define ZROWS 64
#define ZPITCH 132   // words per row in smem (33 float4)

__global__ void __launch_bounds__(64) zproc_kernel(
    const float* __restrict__ Z,
    const float* __restrict__ rmsw,
    const float* __restrict__ Wz)
{
    __shared__ float sX[ZROWS * ZPITCH];               // 33.8 KB
    __shared__ ulonglong2 sW2[512];                    // 8 KB

    for (int i = threadIdx.x; i < 512; i += 64) {
        int t2 = i >> 3, c2 = i & 7;
        int t0 = 2 * t2, t1 = t0 + 1, c0 = 2 * c2, c1 = c0 + 1;
        float r0 = rmsw[t0], r1 = rmsw[t1];
        sW2[i] = make_ulonglong2(pack2(r0 * Wz[t0 * CA + c0], r1 * Wz[t1 * CA + c0]),
                                 pack2(r0 * Wz[t0 * CA + c1], r1 * Wz[t1 * CA + c1]));
    }

    // coalesced stage: 64 contiguous rows = 32 KB contiguous in gmem
    const float4* src = reinterpret_cast<const float4*>(Z + (size_t)blockIdx.x * ZROWS * CT);
#pragma unroll 8
    for (int j = threadIdx.x; j < ZROWS * (CT / 4); j += 64) {
        int row = j >> 5, col = j & 31;
        reinterpret_cast<float4*>(sX)[row * 33 + col] = src[j];
    }
    __syncthreads();

    int r = threadIdx.x;
    const float4* xr = reinterpret_cast<const float4*>(sX) + r * 33;

    u64 acc2[CA];
#pragma unroll
    for (int c = 0; c < CA; c++) acc2[c] = 0ull;
    u64 ss2 = 0ull;

#pragma unroll 4
    for (int i = 0; i < CT / 4; i++) {
        float4 v = xr[i];
        u64 p01 = pack2(v.x, v.y);
        u64 p23 = pack2(v.z, v.w);
        fma2(ss2, p01, p01);
        fma2(ss2, p23, p23);
        const ulonglong2* wa = sW2 + (2 * i) * 8;
        const ulonglong2* wb = sW2 + (2 * i + 1) * 8;
#pragma unroll
        for (int c2 = 0; c2 < 8; c2++) {
            ulonglong2 w = wa[c2];
            fma2(acc2[2 * c2], p01, w.x);
            fma2(acc2[2 * c2 + 1], p01, w.y);
        }
#pragma unroll
        for (int c2 = 0; c2 < 8; c2++) {
            ulonglong2 w = wb[c2];
            fma2(acc2[2 * c2], p23, w.x);
            fma2(acc2[2 * c2 + 1], p23, w.y);
        }
    }

    float sa, sb;
    unpack2(ss2, sa, sb);
    float scale = rsqrtf((sa + sb) * (1.0f / CT) + RMS_EPS);

    float* o = g_Zp + ((size_t)blockIdx.x * ZROWS + r) * CA;
#pragma unroll
    for (int c2 = 0; c2 < 4; c2++) {
        float a0, a1, b0, b1, c0f, c1f, d0, d1;
        unpack2(acc2[4 * c2 + 0], a0, a1);
        unpack2(acc2[4 * c2 + 1], b0, b1);
        unpack2(acc2[4 * c2 + 2], c0f, c1f);
        unpack2(acc2[4 * c2 + 3], d0, d1);
        reinterpret_cast<float4*>(o)[c2] =
            make_float4((a0 + a1) * scale, (b0 + b1) * scale,
                        (c0f + c1f) * scale, (d0 + d1) * scale);
    }
}

// ---------------------------------------------------------------------------
// Kernel 1: S_l / S_m projections. 64 rows / 64-thread block; the 128-float
// rows are staged in two 64-float halves (fits 48KB static smem with both
// weight matrices). Row pitch 68 words -> conflict-free LDS.128.
// ---------------------------------------------------------------------------
#define SPITCH 68    // words per half-row (17 float4)

__global__ void __launch_bounds__(64) sproj_kernel(
    const float* __restrict__ CL,
    const float* __restrict__ Wl,
    const float* __restrict__ Wm)
{
    __shared__ float sX[64 * SPITCH];                  // 17.4 KB
    __shared__ ulonglong2 sWl2[512];                   // 8 KB
    __shared__ ulonglong2 sWm2[512];                   // 8 KB

    for (int i = threadIdx.x; i < 512; i += 64) {
        int t2 = i >> 3, c2 = i & 7;
        int t0 = 2 * t2, t1 = t0 + 1, c0 = 2 * c2, c1 = c0 + 1;
        sWl2[i] = make_ulonglong2(pack2(Wl[t0 * CA + c0], Wl[t1 * CA + c0]),
                                  pack2(Wl[t0 * CA + c1], Wl[t1 * CA + c1]));
        sWm2[i] = make_ulonglong2(pack2(Wm[t0 * CA + c0], Wm[t1 * CA + c0]),
                                  pack2(Wm[t0 * CA + c1], Wm[t1 * CA + c1]));
    }

    int r = threadIdx.x;
    u64 al2[CA], am2[CA];
#pragma unroll
    for (int c = 0; c < CA; c++) { al2[c] = 0ull; am2[c] = 0ull; }

    const float4* src = reinterpret_cast<const float4*>(CL + (size_t)blockIdx.x * 64 * CT);

#pragma unroll 1
    for (int h = 0; h < 2; h++) {
        __syncthreads();
        // stage half h: each row's 64 floats (16 float4), coalesced-ish (256B runs)
#pragma unroll 4
        for (int j = threadIdx.x; j < 64 * 16; j += 64) {
            int row = j >> 4, col = j & 15;
            reinterpret_cast<float4*>(sX)[row * 17 + col] = src[row * 32 + h * 16 + col];
        }
        __syncthreads();

        const float4* xr = reinterpret_cast<const float4*>(sX) + r * 17;
#pragma unroll 4
        for (int i = 0; i < 16; i++) {
            float4 v = xr[i];
            u64 p01 = pack2(fmaxf(v.x, 0.f), fmaxf(v.y, 0.f));
            u64 p23 = pack2(fmaxf(v.z, 0.f), fmaxf(v.w, 0.f));
            int t = h * 16 + i;  // float4-step index within full row
            const ulonglong2* wla = sWl2 + (2 * t) * 8;
            const ulonglong2* wlb = sWl2 + (2 * t + 1) * 8;
            const ulonglong2* wma = sWm2 + (2 * t) * 8;
            const ulonglong2* wmb = sWm2 + (2 * t + 1) * 8;
#pragma unroll
            for (int c2 = 0; c2 < 8; c2++) {
                ulonglong2 w = wla[c2];
                fma2(al2[2 * c2], p01, w.x);
                fma2(al2[2 * c2 + 1], p01, w.y);
            }
#pragma unroll
            for (int c2 = 0; c2 < 8; c2++) {
                ulonglong2 w = wlb[c2];
                fma2(al2[2 * c2], p23, w.x);
                fma2(al2[2 * c2 + 1], p23, w.y);
            }
#pragma unroll
            for (int c2 = 0; c2 < 8; c2++) {
                ulonglong2 w = wma[c2];
                fma2(am2[2 * c2], p01, w.x);
                fma2(am2[2 * c2 + 1], p01, w.y);
            }
#pragma unroll
            for (int c2 = 0; c2 < 8; c2++) {
                ulonglong2 w = wmb[c2];
                fma2(am2[2 * c2], p23, w.x);
                fma2(am2[2 * c2 + 1], p23, w.y);
            }
        }
    }

    size_t row = (size_t)blockIdx.x * 64 + r;
    float* ol = g_Sl + row * CA;
    float* om = g_Sm + row * CA;
#pragma unroll
    for (int c2 = 0; c2 < 4; c2++) {
        float a0, a1, b0, b1, c0f, c1f, d0, d1;
        unpack2(al2[4 * c2 + 0], a0, a1);
        unpack2(al2[4 * c2 + 1], b0, b1);
        unpack2(al2[4 * c2 + 2], c0f, c1f);
        unpack2(al2[4 * c2 + 3], d0, d1);
        reinterpret_cast<float4*>(ol)[c2] = make_float4(a0 + a1, b0 + b1, c0f + c1f, d0 + d1);
        unpack2(am2[4 * c2 + 0], a0, a1);
        unpack2(am2[4 * c2 + 1], b0, b1);
        unpack2(am2[4 * c2 + 2], c0f, c1f);
        unpack2(am2[4 * c2 + 3], d0, d1);
        reinterpret_cast<float4*>(om)[c2] = make_float4(a0 + a1, b0 + b1, c0f + c1f, d0 + d1);
    }
}

// ---------------------------------------------------------------------------
// Kernel 3: pair assembly + residual MLP (f32x2 packed MLP).
// ---------------------------------------------------------------------------
__device__ __forceinline__ void mlp_layer2(const float* in, const ulonglong2* W2, float* out)
{
    u64 acc2[CA];
#pragma unroll
    for (int c = 0; c < CA; c++) acc2[c] = 0ull;
#pragma unroll
    for (int j2 = 0; j2 < 8; j2++) {
        u64 rr = pack2(fmaxf(in[2 * j2], 0.f), fmaxf(in[2 * j2 + 1], 0.f));
#pragma unroll
        for (int c2 = 0; c2 < 8; c2++) {
            ulonglong2 w = W2[j2 * 8 + c2];
            fma2(acc2[2 * c2], rr, w.x);
            fma2(acc2[2 * c2 + 1], rr, w.y);
        }
    }
#pragma unroll
    for (int c = 0; c < CA; c++) {
        float a, b;
        unpack2(acc2[c], a, b);
        out[c] = a + b;
    }
}

__global__ void __launch_bounds__(128) pair_kernel(
    const float* __restrict__ motif_pos,
    const float* __restrict__ is_motif_coord,   // bool serialized as float32
    const float* __restrict__ ref_pos,
    const int* __restrict__ ref_space_uid,
    const float* __restrict__ is_motif_seq,     // bool serialized as float32
    const int* __restrict__ indices,
    const int* __restrict__ tok_idx,
    const float* __restrict__ Wd_m, const float* __restrict__ Wi_m, const float* __restrict__ Wk_m,
    const float* __restrict__ Wd_r, const float* __restrict__ Wi_r, const float* __restrict__ Wk_r,
    const float* __restrict__ W1, const float* __restrict__ W2, const float* __restrict__ W3,
    float* __restrict__ out)
{
    __shared__ float sWd_m[3 * CA], sWi_m[CA], sWk_m[CA];
    __shared__ float sWd_r[3 * CA], sWi_r[CA], sWk_r[CA];
    __shared__ ulonglong2 sW1_2[64], sW2_2[64], sW3_2[64];

    int t = threadIdx.x;
    for (int i = t; i < 3 * CA; i += 128) { sWd_m[i] = Wd_m[i]; sWd_r[i] = Wd_r[i]; }
    for (int i = t; i < CA; i += 128) {
        sWi_m[i] = Wi_m[i]; sWk_m[i] = Wk_m[i];
        sWi_r[i] = Wi_r[i]; sWk_r[i] = Wk_r[i];
    }
    for (int i = t; i < 64; i += 128) {
        int j2 = i >> 3, c2 = i & 7;
        int j0 = 2 * j2, j1 = j0 + 1, c0 = 2 * c2, c1 = c0 + 1;
        sW1_2[i] = make_ulonglong2(pack2(W1[j0 * CA + c0], W1[j1 * CA + c0]),
                                   pack2(W1[j0 * CA + c1], W1[j1 * CA + c1]));
        sW2_2[i] = make_ulonglong2(pack2(W2[j0 * CA + c0], W2[j1 * CA + c0]),
                                   pack2(W2[j0 * CA + c1], W2[j1 * CA + c1]));
        sW3_2[i] = make_ulonglong2(pack2(W3[j0 * CA + c0], W3[j1 * CA + c0]),
                                   pack2(W3[j0 * CA + c1], W3[j1 * CA + c1]));
    }
    __syncthreads();

    int q = blockIdx.x * 4 + (t >> 5);   // query index in [0, B*L)
    if (q >= BN * LN) return;
    int lane = t & 31;                   // k
    int b = q / LN;
    int l = q - b * LN;

    int idx = indices[(size_t)q * KN + lane];
    idx = min(max(idx, 0), LN - 1);

    // issue the long-latency index gather early
    int tk_raw = __ldg(tok_idx + idx);
    int tq_raw = __ldg(tok_idx + l);

    float P[CA];

    // S_l (query, warp-uniform) + S_m gather (key)
    {
        const float4* slp = reinterpret_cast<const float4*>(g_Sl + (size_t)q * CA);
        const float4* smp = reinterpret_cast<const float4*>(g_Sm + ((size_t)b * LN + idx) * CA);
#pragma unroll
        for (int cc = 0; cc < 4; cc++) {
            float4 a = __ldg(slp + cc);
            float4 m = __ldg(smp + cc);
            P[cc * 4 + 0] = a.x + m.x;
            P[cc * 4 + 1] = a.y + m.y;
            P[cc * 4 + 2] = a.z + m.z;
            P[cc * 4 + 3] = a.w + m.w;
        }
    }

    // token-pair Z gather
    {
        int tq = min(max(tq_raw, 0), IN - 1);
        int tk = min(max(tk_raw, 0), IN - 1);
        const float4* zp = reinterpret_cast<const float4*>(g_Zp + ((size_t)tq * IN + tk) * CA);
#pragma unroll
        for (int cc = 0; cc < 4; cc++) {
            float4 z = __ldg(zp + cc);
            P[cc * 4 + 0] += z.x;
            P[cc * 4 + 1] += z.y;
            P[cc * 4 + 2] += z.z;
            P[cc * 4 + 3] += z.w;
        }
    }

    // motif-position branch: query mask AND key mask (0/1 masks)
    if (is_motif_coord[l] != 0.f && is_motif_coord[idx] != 0.f) {
        float dx = motif_pos[l * 3 + 0] - motif_pos[idx * 3 + 0];
        float dy = motif_pos[l * 3 + 1] - motif_pos[idx * 3 + 1];
        float dz = motif_pos[l * 3 + 2] - motif_pos[idx * 3 + 2];
        float inv = 1.0f / (1.0f + dx * dx + dy * dy + dz * dz);
#pragma unroll
        for (int c = 0; c < CA; c++)
            P[c] += dx * sWd_m[c] + dy * sWd_m[CA + c] + dz * sWd_m[2 * CA + c]
                  + inv * sWi_m[c] + sWk_m[c];
    }

    // ref-position branch: query is_motif_seq AND (same uid AND key is_motif_seq)
    if (is_motif_seq[l] != 0.f) {
        if (ref_space_uid[idx] == ref_space_uid[l] && is_motif_seq[idx] != 0.f) {
            float dx = ref_pos[l * 3 + 0] - ref_pos[idx * 3 + 0];
            float dy = ref_pos[l * 3 + 1] - ref_pos[idx * 3 + 1];
            float dz = ref_pos[l * 3 + 2] - ref_pos[idx * 3 + 2];
            float inv = 1.0f / (1.0f + dx * dx + dy * dy + dz * dz);
#pragma unroll
            for (int c = 0; c < CA; c++)
                P[c] += dx * sWd_r[c] + dy * sWd_r[CA + c] + dz * sWd_r[2 * CA + c]
                      + inv * sWi_r[c] + sWk_r[c];
        }
    }

    // residual MLP: h = relu->W1 -> relu->W2 -> relu->W3 ; out = P + h
    float h0[CA], h1[CA];
    mlp_layer2(P,  sW1_2, h0);
    mlp_layer2(h0, sW2_2, h1);
    mlp_layer2(h1, sW3_2, h0);

    float4* op = reinterpret_cast<float4*>(out + ((size_t)q * KN + lane) * CA);
#pragma unroll
    for (int cc = 0; cc < 4; cc++)
        op[cc] = make_float4(P[cc * 4 + 0] + h0[cc * 4 + 0],
                             P[cc * 4 + 1] + h0[cc * 4 + 1],
                             P[cc * 4 + 2] + h0[cc * 4 + 2],
                             P[cc * 4 + 3] + h0[cc * 4 + 3]);
}

// ---------------------------------------------------------------------------
extern "C" void kernel_launch(void* const* d_in, const int* in_sizes, int n_in,
                              void* d_out, int out_size)
{
    const float* motif_pos      = (const float*)d_in[0];
    const float* is_motif_coord = (const float*)d_in[1];
    const float* ref_pos        = (const float*)d_in[2];
    const int*   ref_space_uid  = (const int*)d_in[3];
    const float* is_motif_seq   = (const float*)d_in[4];
    const int*   indices        = (const int*)d_in[5];
    const float* C_L            = (const float*)d_in[6];
    const float* Z              = (const float*)d_in[7];
    const int*   tok_idx        = (const int*)d_in[8];
    const float* W_d_m          = (const float*)d_in[9];
    const float* W_inv_m        = (const float*)d_in[10];
    const float* W_mask_m       = (const float*)d_in[11];
    const float* W_d_r          = (const float*)d_in[12];
    const float* W_inv_r        = (const float*)d_in[13];
    const float* W_mask_r       = (const float*)d_in[14];
    const float* W_single_l     = (const float*)d_in[15];
    const float* W_single_m     = (const float*)d_in[16];
    const float* rms_w          = (const float*)d_in[17];
    const float* W_z            = (const float*)d_in[18];
    const float* W_mlp1         = (const float*)d_in[19];
    const float* W_mlp2         = (const float*)d_in[20];
    const float* W_mlp3         = (const float*)d_in[21];
    float* out = (float*)d_out;

    // zproc first: it's the dominant kernel and this puts it under ncu's
    // fixed launch-skip sample window.
    zproc_kernel<<<(IN * IN) / ZROWS, 64>>>(Z, rms_w, W_z);
    sproj_kernel<<<(BN * LN) / 64, 64>>>(C_L, W_single_l, W_single_m);
    pair_kernel<<<(BN * LN + 3) / 4, 128>>>(
        motif_pos, is_motif_coord, ref_pos, ref_space_uid, is_motif_seq,
        indices, tok_idx,
        W_d_m, W_inv_m, W_mask_m, W_d_r, W_inv_r, W_mask_r,
        W_mlp1, W_mlp2, W_mlp3, out);
}

// round 5
// speedup vs baseline: 1.3080x; 1.2041x over previous
#include <cuda_runtime.h>

#define BN 2
#define LN 12288
#define KN 32
#define IN 768
#define CT 128
#define CA 16
#define RMS_EPS 1e-6f

typedef unsigned long long u64;

// Scratch (allocs are banned; device globals are the sanctioned workaround)
__device__ float g_Sl[BN * LN * CA];                  // 1.5 MB
__device__ float g_Sm[BN * LN * CA];                  // 1.5 MB
__device__ float g_Zp[(size_t)IN * IN * CA];          // 37.75 MB
__device__ float4 g_atom[LN];                         // packed per-atom metadata

// ---- packed f32x2 helpers (sm_100+) ---------------------------------------
__device__ __forceinline__ u64 pack2(float a, float b) {
    u64 v;
    asm("mov.b64 %0, {%1, %2};" : "=l"(v) : "r"(__float_as_uint(a)), "r"(__float_as_uint(b)));
    return v;
}
__device__ __forceinline__ void unpack2(u64 v, float& a, float& b) {
    unsigned x, y;
    asm("mov.b64 {%0, %1}, %2;" : "=r"(x), "=r"(y) : "l"(v));
    a = __uint_as_float(x); b = __uint_as_float(y);
}
__device__ __forceinline__ void fma2(u64& d, u64 a, u64 b) {
    asm("fma.rn.f32x2 %0, %1, %2, %0;" : "+l"(d) : "l"(a), "l"(b));
}
__device__ __forceinline__ void cp_async16(void* smem_dst, const void* gmem_src) {
    unsigned s = (unsigned)__cvta_generic_to_shared(smem_dst);
    asm volatile("cp.async.cg.shared.global [%0], [%1], 16;\n" :: "r"(s), "l"(gmem_src));
}
__device__ __forceinline__ void cp_async_wait_all() {
    asm volatile("cp.async.commit_group;\ncp.async.wait_group 0;\n" ::: "memory");
}

// ---------------------------------------------------------------------------
// Kernel 2 (first, dominant): Z_proc = rmsnorm(Z)*rms_w @ W_z.
// 128 rows / 64-thread block, 2 rows per thread (r and r+64): the per-row
// broadcast weight LDS stream is amortized over 2 rows. X staged per K-half
// via cp.async, pitch 17 float4 (68 words == 4 mod 32 -> conflict-free).
// ---------------------------------------------------------------------------
#define ZR 128

__global__ void __launch_bounds__(64) zproc_kernel(
    const float* __restrict__ Z,
    const float* __restrict__ rmsw,
    const float* __restrict__ Wz)
{
    __shared__ float4 sX[ZR * 17];                     // 34.8 KB (one K-half)
    __shared__ ulonglong2 sW2[512];                    // 8 KB

    for (int i = threadIdx.x; i < 512; i += 64) {
        int t2 = i >> 3, c2 = i & 7;
        int t0 = 2 * t2, t1 = t0 + 1, c0 = 2 * c2, c1 = c0 + 1;
        float r0 = rmsw[t0], r1 = rmsw[t1];
        sW2[i] = make_ulonglong2(pack2(r0 * Wz[t0 * CA + c0], r1 * Wz[t1 * CA + c0]),
                                 pack2(r0 * Wz[t0 * CA + c1], r1 * Wz[t1 * CA + c1]));
    }

    int r = threadIdx.x;
    const float4* src = reinterpret_cast<const float4*>(Z) + (size_t)blockIdx.x * ZR * 32;

    u64 accA[CA], accB[CA];
#pragma unroll
    for (int c = 0; c < CA; c++) { accA[c] = 0ull; accB[c] = 0ull; }
    u64 ssA = 0ull, ssB = 0ull;

#pragma unroll 1
    for (int h = 0; h < 2; h++) {
        __syncthreads();
#pragma unroll 8
        for (int j = threadIdx.x; j < ZR * 16; j += 64) {
            int row = j >> 4, col = j & 15;
            cp_async16(&sX[row * 17 + col], src + row * 32 + h * 16 + col);
        }
        cp_async_wait_all();
        __syncthreads();

#pragma unroll 4
        for (int i = 0; i < 16; i++) {
            float4 vA = sX[r * 17 + i];
            float4 vB = sX[(r + 64) * 17 + i];
            u64 a01 = pack2(vA.x, vA.y), a23 = pack2(vA.z, vA.w);
            u64 b01 = pack2(vB.x, vB.y), b23 = pack2(vB.z, vB.w);
            fma2(ssA, a01, a01); fma2(ssA, a23, a23);
            fma2(ssB, b01, b01); fma2(ssB, b23, b23);
            int t = h * 16 + i;
            const ulonglong2* wa = sW2 + (2 * t) * 8;
            const ulonglong2* wb = sW2 + (2 * t + 1) * 8;
#pragma unroll
            for (int c2 = 0; c2 < 8; c2++) {
                ulonglong2 w = wa[c2];
                fma2(accA[2 * c2], a01, w.x);
                fma2(accA[2 * c2 + 1], a01, w.y);
                fma2(accB[2 * c2], b01, w.x);
                fma2(accB[2 * c2 + 1], b01, w.y);
            }
#pragma unroll
            for (int c2 = 0; c2 < 8; c2++) {
                ulonglong2 w = wb[c2];
                fma2(accA[2 * c2], a23, w.x);
                fma2(accA[2 * c2 + 1], a23, w.y);
                fma2(accB[2 * c2], b23, w.x);
                fma2(accB[2 * c2 + 1], b23, w.y);
            }
        }
    }

    float sa, sb;
    unpack2(ssA, sa, sb);
    float scaleA = rsqrtf((sa + sb) * (1.0f / CT) + RMS_EPS);
    unpack2(ssB, sa, sb);
    float scaleB = rsqrtf((sa + sb) * (1.0f / CT) + RMS_EPS);

    float* oA = g_Zp + ((size_t)blockIdx.x * ZR + r) * CA;
    float* oB = g_Zp + ((size_t)blockIdx.x * ZR + r + 64) * CA;
#pragma unroll
    for (int c2 = 0; c2 < 4; c2++) {
        float a0, a1, b0, b1, c0f, c1f, d0, d1;
        unpack2(accA[4 * c2 + 0], a0, a1);
        unpack2(accA[4 * c2 + 1], b0, b1);
        unpack2(accA[4 * c2 + 2], c0f, c1f);
        unpack2(accA[4 * c2 + 3], d0, d1);
        reinterpret_cast<float4*>(oA)[c2] =
            make_float4((a0 + a1) * scaleA, (b0 + b1) * scaleA,
                        (c0f + c1f) * scaleA, (d0 + d1) * scaleA);
        unpack2(accB[4 * c2 + 0], a0, a1);
        unpack2(accB[4 * c2 + 1], b0, b1);
        unpack2(accB[4 * c2 + 2], c0f, c1f);
        unpack2(accB[4 * c2 + 3], d0, d1);
        reinterpret_cast<float4*>(oB)[c2] =
            make_float4((a0 + a1) * scaleB, (b0 + b1) * scaleB,
                        (c0f + c1f) * scaleB, (d0 + d1) * scaleB);
    }
}

// ---------------------------------------------------------------------------
// Kernel 1: S_l / S_m projections (R4 version, ~10us).
// ---------------------------------------------------------------------------
__global__ void __launch_bounds__(64) sproj_kernel(
    const float* __restrict__ CL,
    const float* __restrict__ Wl,
    const float* __restrict__ Wm)
{
    __shared__ float sX[64 * 68];
    __shared__ ulonglong2 sWl2[512];
    __shared__ ulonglong2 sWm2[512];

    for (int i = threadIdx.x; i < 512; i += 64) {
        int t2 = i >> 3, c2 = i & 7;
        int t0 = 2 * t2, t1 = t0 + 1, c0 = 2 * c2, c1 = c0 + 1;
        sWl2[i] = make_ulonglong2(pack2(Wl[t0 * CA + c0], Wl[t1 * CA + c0]),
                                  pack2(Wl[t0 * CA + c1], Wl[t1 * CA + c1]));
        sWm2[i] = make_ulonglong2(pack2(Wm[t0 * CA + c0], Wm[t1 * CA + c0]),
                                  pack2(Wm[t0 * CA + c1], Wm[t1 * CA + c1]));
    }

    int r = threadIdx.x;
    u64 al2[CA], am2[CA];
#pragma unroll
    for (int c = 0; c < CA; c++) { al2[c] = 0ull; am2[c] = 0ull; }

    const float4* src = reinterpret_cast<const float4*>(CL + (size_t)blockIdx.x * 64 * CT);

#pragma unroll 1
    for (int h = 0; h < 2; h++) {
        __syncthreads();
#pragma unroll 4
        for (int j = threadIdx.x; j < 64 * 16; j += 64) {
            int row = j >> 4, col = j & 15;
            cp_async16(&reinterpret_cast<float4*>(sX)[row * 17 + col],
                       src + row * 32 + h * 16 + col);
        }
        cp_async_wait_all();
        __syncthreads();

        const float4* xr = reinterpret_cast<const float4*>(sX) + r * 17;
#pragma unroll 4
        for (int i = 0; i < 16; i++) {
            float4 v = xr[i];
            u64 p01 = pack2(fmaxf(v.x, 0.f), fmaxf(v.y, 0.f));
            u64 p23 = pack2(fmaxf(v.z, 0.f), fmaxf(v.w, 0.f));
            int t = h * 16 + i;
            const ulonglong2* wla = sWl2 + (2 * t) * 8;
            const ulonglong2* wlb = sWl2 + (2 * t + 1) * 8;
            const ulonglong2* wma = sWm2 + (2 * t) * 8;
            const ulonglong2* wmb = sWm2 + (2 * t + 1) * 8;
#pragma unroll
            for (int c2 = 0; c2 < 8; c2++) {
                ulonglong2 w = wla[c2];
                fma2(al2[2 * c2], p01, w.x);
                fma2(al2[2 * c2 + 1], p01, w.y);
            }
#pragma unroll
            for (int c2 = 0; c2 < 8; c2++) {
                ulonglong2 w = wlb[c2];
                fma2(al2[2 * c2], p23, w.x);
                fma2(al2[2 * c2 + 1], p23, w.y);
            }
#pragma unroll
            for (int c2 = 0; c2 < 8; c2++) {
                ulonglong2 w = wma[c2];
                fma2(am2[2 * c2], p01, w.x);
                fma2(am2[2 * c2 + 1], p01, w.y);
            }
#pragma unroll
            for (int c2 = 0; c2 < 8; c2++) {
                ulonglong2 w = wmb[c2];
                fma2(am2[2 * c2], p23, w.x);
                fma2(am2[2 * c2 + 1], p23, w.y);
            }
        }
    }

    size_t row = (size_t)blockIdx.x * 64 + r;
    float* ol = g_Sl + row * CA;
    float* om = g_Sm + row * CA;
#pragma unroll
    for (int c2 = 0; c2 < 4; c2++) {
        float a0, a1, b0, b1, c0f, c1f, d0, d1;
        unpack2(al2[4 * c2 + 0], a0, a1);
        unpack2(al2[4 * c2 + 1], b0, b1);
        unpack2(al2[4 * c2 + 2], c0f, c1f);
        unpack2(al2[4 * c2 + 3], d0, d1);
        reinterpret_cast<float4*>(ol)[c2] = make_float4(a0 + a1, b0 + b1, c0f + c1f, d0 + d1);
        unpack2(am2[4 * c2 + 0], a0, a1);
        unpack2(am2[4 * c2 + 1], b0, b1);
        unpack2(am2[4 * c2 + 2], c0f, c1f);
        unpack2(am2[4 * c2 + 3], d0, d1);
        reinterpret_cast<float4*>(om)[c2] = make_float4(a0 + a1, b0 + b1, c0f + c1f, d0 + d1);
    }
}

// ---------------------------------------------------------------------------
// Kernel 0: pack per-atom metadata into one 16B record ->
// one scattered LDG.128 per key instead of four scattered LDG.32.
// ---------------------------------------------------------------------------
__global__ void pack_atoms_kernel(
    const float* __restrict__ is_motif_coord,
    const float* __restrict__ is_motif_seq,
    const int* __restrict__ ref_space_uid,
    const int* __restrict__ tok_idx)
{
    int i = blockIdx.x * blockDim.x + threadIdx.x;
    if (i >= LN) return;
    g_atom[i] = make_float4(is_motif_coord[i], is_motif_seq[i],
                            __int_as_float(ref_space_uid[i]),
                            __int_as_float(min(max(tok_idx[i], 0), IN - 1)));
}

// ---------------------------------------------------------------------------
// Kernel 3: pair assembly + residual MLP (f32x2 packed MLP).
// ---------------------------------------------------------------------------
__device__ __forceinline__ void mlp_layer2(const float* in, const ulonglong2* W2, float* out)
{
    u64 acc2[CA];
#pragma unroll
    for (int c = 0; c < CA; c++) acc2[c] = 0ull;
#pragma unroll
    for (int j2 = 0; j2 < 8; j2++) {
        u64 rr = pack2(fmaxf(in[2 * j2], 0.f), fmaxf(in[2 * j2 + 1], 0.f));
#pragma unroll
        for (int c2 = 0; c2 < 8; c2++) {
            ulonglong2 w = W2[j2 * 8 + c2];
            fma2(acc2[2 * c2], rr, w.x);
            fma2(acc2[2 * c2 + 1], rr, w.y);
        }
    }
#pragma unroll
    for (int c = 0; c < CA; c++) {
        float a, b;
        unpack2(acc2[c], a, b);
        out[c] = a + b;
    }
}

__global__ void __launch_bounds__(128) pair_kernel(
    const float* __restrict__ motif_pos,
    const float* __restrict__ ref_pos,
    const int* __restrict__ indices,
    const float* __restrict__ Wd_m, const float* __restrict__ Wi_m, const float* __restrict__ Wk_m,
    const float* __restrict__ Wd_r, const float* __restrict__ Wi_r, const float* __restrict__ Wk_r,
    const float* __restrict__ W1, const float* __restrict__ W2, const float* __restrict__ W3,
    float* __restrict__ out)
{
    __shared__ float sWd_m[3 * CA], sWi_m[CA], sWk_m[CA];
    __shared__ float sWd_r[3 * CA], sWi_r[CA], sWk_r[CA];
    __shared__ ulonglong2 sW1_2[64], sW2_2[64], sW3_2[64];

    int t = threadIdx.x;
    for (int i = t; i < 3 * CA; i += 128) { sWd_m[i] = Wd_m[i]; sWd_r[i] = Wd_r[i]; }
    for (int i = t; i < CA; i += 128) {
        sWi_m[i] = Wi_m[i]; sWk_m[i] = Wk_m[i];
        sWi_r[i] = Wi_r[i]; sWk_r[i] = Wk_r[i];
    }
    for (int i = t; i < 64; i += 128) {
        int j2 = i >> 3, c2 = i & 7;
        int j0 = 2 * j2, j1 = j0 + 1, c0 = 2 * c2, c1 = c0 + 1;
        sW1_2[i] = make_ulonglong2(pack2(W1[j0 * CA + c0], W1[j1 * CA + c0]),
                                   pack2(W1[j0 * CA + c1], W1[j1 * CA + c1]));
        sW2_2[i] = make_ulonglong2(pack2(W2[j0 * CA + c0], W2[j1 * CA + c0]),
                                   pack2(W2[j0 * CA + c1], W2[j1 * CA + c1]));
        sW3_2[i] = make_ulonglong2(pack2(W3[j0 * CA + c0], W3[j1 * CA + c0]),
                                   pack2(W3[j0 * CA + c1], W3[j1 * CA + c1]));
    }
    __syncthreads();

    int q = blockIdx.x * 4 + (t >> 5);   // query index in [0, B*L)
    if (q >= BN * LN) return;
    int lane = t & 31;                   // k
    int b = q / LN;
    int l = q - b * LN;

    int idx = indices[(size_t)q * KN + lane];
    idx = min(max(idx, 0), LN - 1);

    // key + query metadata (query is warp-uniform)
    float4 ka = __ldg(g_atom + idx);
    float4 qa = __ldg(g_atom + l);
    int tk = __float_as_int(ka.w);
    int tq = __float_as_int(qa.w);

    float P[CA];

    // S_l (query, warp-uniform) + S_m gather (key)
    {
        const float4* slp = reinterpret_cast<const float4*>(g_Sl + (size_t)q * CA);
        const float4* smp = reinterpret_cast<const float4*>(g_Sm + ((size_t)b * LN + idx) * CA);
#pragma unroll
        for (int cc = 0; cc < 4; cc++) {
            float4 a = __ldg(slp + cc);
            float4 m = __ldg(smp + cc);
            P[cc * 4 + 0] = a.x + m.x;
            P[cc * 4 + 1] = a.y + m.y;
            P[cc * 4 + 2] = a.z + m.z;
            P[cc * 4 + 3] = a.w + m.w;
        }
    }

    // token-pair Z gather
    {
        const float4* zp = reinterpret_cast<const float4*>(g_Zp + ((size_t)tq * IN + tk) * CA);
#pragma unroll
        for (int cc = 0; cc < 4; cc++) {
            float4 z = __ldg(zp + cc);
            P[cc * 4 + 0] += z.x;
            P[cc * 4 + 1] += z.y;
            P[cc * 4 + 2] += z.z;
            P[cc * 4 + 3] += z.w;
        }
    }

    // motif-position branch: query mask AND key mask (0/1 masks)
    if (qa.x != 0.f && ka.x != 0.f) {
        float dx = motif_pos[l * 3 + 0] - motif_pos[idx * 3 + 0];
        float dy = motif_pos[l * 3 + 1] - motif_pos[idx * 3 + 1];
        float dz = motif_pos[l * 3 + 2] - motif_pos[idx * 3 + 2];
        float inv = 1.0f / (1.0f + dx * dx + dy * dy + dz * dz);
#pragma unroll
        for (int c = 0; c < CA; c++)
            P[c] += dx * sWd_m[c] + dy * sWd_m[CA + c] + dz * sWd_m[2 * CA + c]
                  + inv * sWi_m[c] + sWk_m[c];
    }

    // ref-position branch: query is_motif_seq AND (same uid AND key is_motif_seq)
    if (qa.y != 0.f && __float_as_int(ka.z) == __float_as_int(qa.z) && ka.y != 0.f) {
        float dx = ref_pos[l * 3 + 0] - ref_pos[idx * 3 + 0];
        float dy = ref_pos[l * 3 + 1] - ref_pos[idx * 3 + 1];
        float dz = ref_pos[l * 3 + 2] - ref_pos[idx * 3 + 2];
        float inv = 1.0f / (1.0f + dx * dx + dy * dy + dz * dz);
#pragma unroll
        for (int c = 0; c < CA; c++)
            P[c] += dx * sWd_r[c] + dy * sWd_r[CA + c] + dz * sWd_r[2 * CA + c]
                  + inv * sWi_r[c] + sWk_r[c];
    }

    // residual MLP: h = relu->W1 -> relu->W2 -> relu->W3 ; out = P + h
    float h0[CA], h1[CA];
    mlp_layer2(P,  sW1_2, h0);
    mlp_layer2(h0, sW2_2, h1);
    mlp_layer2(h1, sW3_2, h0);

    float4* op = reinterpret_cast<float4*>(out + ((size_t)q * KN + lane) * CA);
#pragma unroll
    for (int cc = 0; cc < 4; cc++)
        op[cc] = make_float4(P[cc * 4 + 0] + h0[cc * 4 + 0],
                             P[cc * 4 + 1] + h0[cc * 4 + 1],
                             P[cc * 4 + 2] + h0[cc * 4 + 2],
                             P[cc * 4 + 3] + h0[cc * 4 + 3]);
}

// ---------------------------------------------------------------------------
extern "C" void kernel_launch(void* const* d_in, const int* in_sizes, int n_in,
                              void* d_out, int out_size)
{
    const float* motif_pos      = (const float*)d_in[0];
    const float* is_motif_coord = (const float*)d_in[1];
    const float* ref_pos        = (const float*)d_in[2];
    const int*   ref_space_uid  = (const int*)d_in[3];
    const float* is_motif_seq   = (const float*)d_in[4];
    const int*   indices        = (const int*)d_in[5];
    const float* C_L            = (const float*)d_in[6];
    const float* Z              = (const float*)d_in[7];
    const int*   tok_idx        = (const int*)d_in[8];
    const float* W_d_m          = (const float*)d_in[9];
    const float* W_inv_m        = (const float*)d_in[10];
    const float* W_mask_m       = (const float*)d_in[11];
    const float* W_d_r          = (const float*)d_in[12];
    const float* W_inv_r        = (const float*)d_in[13];
    const float* W_mask_r       = (const float*)d_in[14];
    const float* W_single_l     = (const float*)d_in[15];
    const float* W_single_m     = (const float*)d_in[16];
    const float* rms_w          = (const float*)d_in[17];
    const float* W_z            = (const float*)d_in[18];
    const float* W_mlp1         = (const float*)d_in[19];
    const float* W_mlp2         = (const float*)d_in[20];
    const float* W_mlp3         = (const float*)d_in[21];
    float* out = (float*)d_out;

    zproc_kernel<<<(IN * IN) / ZR, 64>>>(Z, rms_w, W_z);
    pack_atoms_kernel<<<(LN + 127) / 128, 128>>>(is_motif_coord, is_motif_seq,
                                                 ref_space_uid, tok_idx);
    sproj_kernel<<<(BN * LN) / 64, 64>>>(C_L, W_single_l, W_single_m);
    pair_kernel<<<(BN * LN + 3) / 4, 128>>>(
        motif_pos, ref_pos, indices,
        W_d_m, W_inv_m, W_mask_m, W_d_r, W_inv_r, W_mask_r,
        W_mlp1, W_mlp2, W_mlp3, out);
}

// round 6
// speedup vs baseline: 1.5107x; 1.1549x over previous
#include <cuda_runtime.h>

#define BN 2
#define LN 12288
#define KN 32
#define IN 768
#define CT 128
#define CA 16
#define RMS_EPS 1e-6f

typedef unsigned long long u64;

// Scratch (allocs are banned; device globals are the sanctioned workaround)
__device__ float g_Sl[BN * LN * CA];                  // 1.5 MB
__device__ float g_Sm[BN * LN * CA];                  // 1.5 MB
__device__ float g_Zp[(size_t)IN * IN * CA];          // 37.75 MB
__device__ float4 g_atom[LN];                         // packed per-atom metadata

// ---- packed f32x2 helpers (sm_100+) ---------------------------------------
__device__ __forceinline__ u64 pack2(float a, float b) {
    u64 v;
    asm("mov.b64 %0, {%1, %2};" : "=l"(v) : "r"(__float_as_uint(a)), "r"(__float_as_uint(b)));
    return v;
}
__device__ __forceinline__ void unpack2(u64 v, float& a, float& b) {
    unsigned x, y;
    asm("mov.b64 {%0, %1}, %2;" : "=r"(x), "=r"(y) : "l"(v));
    a = __uint_as_float(x); b = __uint_as_float(y);
}
__device__ __forceinline__ void fma2(u64& d, u64 a, u64 b) {
    asm("fma.rn.f32x2 %0, %1, %2, %0;" : "+l"(d) : "l"(a), "l"(b));
}
__device__ __forceinline__ void cp_async16(void* smem_dst, const void* gmem_src) {
    unsigned s = (unsigned)__cvta_generic_to_shared(smem_dst);
    asm volatile("cp.async.cg.shared.global [%0], [%1], 16;\n" :: "r"(s), "l"(gmem_src));
}
__device__ __forceinline__ void cp_async_wait_all() {
    asm volatile("cp.async.commit_group;\ncp.async.wait_group 0;\n" ::: "memory");
}

// ---------------------------------------------------------------------------
// Kernel 2 (first, dominant): Z_proc = rmsnorm(Z)*rms_w @ W_z.
// 256 rows / 128-thread block, 2 rows per thread (r, r+128). K staged in
// 4 chunks of 32 floats (8 float4), pitch 9 float4 (36 words == 4 mod 32).
// 20 warps/SM resident (vs 12 in R5) -> more DRAM concurrency.
// ---------------------------------------------------------------------------
#define ZR2 256

__global__ void __launch_bounds__(128) zproc_kernel(
    const float* __restrict__ Z,
    const float* __restrict__ rmsw,
    const float* __restrict__ Wz)
{
    __shared__ float4 sX[ZR2 * 9];                     // 36.9 KB (one K-quarter)
    __shared__ ulonglong2 sW2[512];                    // 8 KB

    for (int i = threadIdx.x; i < 512; i += 128) {
        int t2 = i >> 3, c2 = i & 7;
        int t0 = 2 * t2, t1 = t0 + 1, c0 = 2 * c2, c1 = c0 + 1;
        float r0 = rmsw[t0], r1 = rmsw[t1];
        sW2[i] = make_ulonglong2(pack2(r0 * Wz[t0 * CA + c0], r1 * Wz[t1 * CA + c0]),
                                 pack2(r0 * Wz[t0 * CA + c1], r1 * Wz[t1 * CA + c1]));
    }

    int r = threadIdx.x;
    const float4* src = reinterpret_cast<const float4*>(Z) + (size_t)blockIdx.x * ZR2 * 32;

    u64 accA[CA], accB[CA];
#pragma unroll
    for (int c = 0; c < CA; c++) { accA[c] = 0ull; accB[c] = 0ull; }
    u64 ssA = 0ull, ssB = 0ull;

#pragma unroll 1
    for (int h = 0; h < 4; h++) {
        __syncthreads();
        // stage K-quarter h: 256 rows x 8 float4, coalesced 128B runs
#pragma unroll 4
        for (int j = threadIdx.x; j < ZR2 * 8; j += 128) {
            int row = j >> 3, col = j & 7;
            cp_async16(&sX[row * 9 + col], src + row * 32 + h * 8 + col);
        }
        cp_async_wait_all();
        __syncthreads();

#pragma unroll 4
        for (int i = 0; i < 8; i++) {
            float4 vA = sX[r * 9 + i];
            float4 vB = sX[(r + 128) * 9 + i];
            u64 a01 = pack2(vA.x, vA.y), a23 = pack2(vA.z, vA.w);
            u64 b01 = pack2(vB.x, vB.y), b23 = pack2(vB.z, vB.w);
            fma2(ssA, a01, a01); fma2(ssA, a23, a23);
            fma2(ssB, b01, b01); fma2(ssB, b23, b23);
            int t = h * 8 + i;                         // float4-group index 0..31
            const ulonglong2* wa = sW2 + (2 * t) * 8;
            const ulonglong2* wb = sW2 + (2 * t + 1) * 8;
#pragma unroll
            for (int c2 = 0; c2 < 8; c2++) {
                ulonglong2 w = wa[c2];
                fma2(accA[2 * c2], a01, w.x);
                fma2(accA[2 * c2 + 1], a01, w.y);
                fma2(accB[2 * c2], b01, w.x);
                fma2(accB[2 * c2 + 1], b01, w.y);
            }
#pragma unroll
            for (int c2 = 0; c2 < 8; c2++) {
                ulonglong2 w = wb[c2];
                fma2(accA[2 * c2], a23, w.x);
                fma2(accA[2 * c2 + 1], a23, w.y);
                fma2(accB[2 * c2], b23, w.x);
                fma2(accB[2 * c2 + 1], b23, w.y);
            }
        }
    }

    float sa, sb;
    unpack2(ssA, sa, sb);
    float scaleA = rsqrtf((sa + sb) * (1.0f / CT) + RMS_EPS);
    unpack2(ssB, sa, sb);
    float scaleB = rsqrtf((sa + sb) * (1.0f / CT) + RMS_EPS);

    float* oA = g_Zp + ((size_t)blockIdx.x * ZR2 + r) * CA;
    float* oB = g_Zp + ((size_t)blockIdx.x * ZR2 + r + 128) * CA;
#pragma unroll
    for (int c2 = 0; c2 < 4; c2++) {
        float a0, a1, b0, b1, c0f, c1f, d0, d1;
        unpack2(accA[4 * c2 + 0], a0, a1);
        unpack2(accA[4 * c2 + 1], b0, b1);
        unpack2(accA[4 * c2 + 2], c0f, c1f);
        unpack2(accA[4 * c2 + 3], d0, d1);
        reinterpret_cast<float4*>(oA)[c2] =
            make_float4((a0 + a1) * scaleA, (b0 + b1) * scaleA,
                        (c0f + c1f) * scaleA, (d0 + d1) * scaleA);
        unpack2(accB[4 * c2 + 0], a0, a1);
        unpack2(accB[4 * c2 + 1], b0, b1);
        unpack2(accB[4 * c2 + 2], c0f, c1f);
        unpack2(accB[4 * c2 + 3], d0, d1);
        reinterpret_cast<float4*>(oB)[c2] =
            make_float4((a0 + a1) * scaleB, (b0 + b1) * scaleB,
                        (c0f + c1f) * scaleB, (d0 + d1) * scaleB);
    }
}

// ---------------------------------------------------------------------------
// Kernel 1: S_l / S_m projections (unchanged from R5, ~10us).
// ---------------------------------------------------------------------------
__global__ void __launch_bounds__(64) sproj_kernel(
    const float* __restrict__ CL,
    const float* __restrict__ Wl,
    const float* __restrict__ Wm)
{
    __shared__ float sX[64 * 68];
    __shared__ ulonglong2 sWl2[512];
    __shared__ ulonglong2 sWm2[512];

    for (int i = threadIdx.x; i < 512; i += 64) {
        int t2 = i >> 3, c2 = i & 7;
        int t0 = 2 * t2, t1 = t0 + 1, c0 = 2 * c2, c1 = c0 + 1;
        sWl2[i] = make_ulonglong2(pack2(Wl[t0 * CA + c0], Wl[t1 * CA + c0]),
                                  pack2(Wl[t0 * CA + c1], Wl[t1 * CA + c1]));
        sWm2[i] = make_ulonglong2(pack2(Wm[t0 * CA + c0], Wm[t1 * CA + c0]),
                                  pack2(Wm[t0 * CA + c1], Wm[t1 * CA + c1]));
    }

    int r = threadIdx.x;
    u64 al2[CA], am2[CA];
#pragma unroll
    for (int c = 0; c < CA; c++) { al2[c] = 0ull; am2[c] = 0ull; }

    const float4* src = reinterpret_cast<const float4*>(CL + (size_t)blockIdx.x * 64 * CT);

#pragma unroll 1
    for (int h = 0; h < 2; h++) {
        __syncthreads();
#pragma unroll 4
        for (int j = threadIdx.x; j < 64 * 16; j += 64) {
            int row = j >> 4, col = j & 15;
            cp_async16(&reinterpret_cast<float4*>(sX)[row * 17 + col],
                       src + row * 32 + h * 16 + col);
        }
        cp_async_wait_all();
        __syncthreads();

        const float4* xr = reinterpret_cast<const float4*>(sX) + r * 17;
#pragma unroll 4
        for (int i = 0; i < 16; i++) {
            float4 v = xr[i];
            u64 p01 = pack2(fmaxf(v.x, 0.f), fmaxf(v.y, 0.f));
            u64 p23 = pack2(fmaxf(v.z, 0.f), fmaxf(v.w, 0.f));
            int t = h * 16 + i;
            const ulonglong2* wla = sWl2 + (2 * t) * 8;
            const ulonglong2* wlb = sWl2 + (2 * t + 1) * 8;
            const ulonglong2* wma = sWm2 + (2 * t) * 8;
            const ulonglong2* wmb = sWm2 + (2 * t + 1) * 8;
#pragma unroll
            for (int c2 = 0; c2 < 8; c2++) {
                ulonglong2 w = wla[c2];
                fma2(al2[2 * c2], p01, w.x);
                fma2(al2[2 * c2 + 1], p01, w.y);
            }
#pragma unroll
            for (int c2 = 0; c2 < 8; c2++) {
                ulonglong2 w = wlb[c2];
                fma2(al2[2 * c2], p23, w.x);
                fma2(al2[2 * c2 + 1], p23, w.y);
            }
#pragma unroll
            for (int c2 = 0; c2 < 8; c2++) {
                ulonglong2 w = wma[c2];
                fma2(am2[2 * c2], p01, w.x);
                fma2(am2[2 * c2 + 1], p01, w.y);
            }
#pragma unroll
            for (int c2 = 0; c2 < 8; c2++) {
                ulonglong2 w = wmb[c2];
                fma2(am2[2 * c2], p23, w.x);
                fma2(am2[2 * c2 + 1], p23, w.y);
            }
        }
    }

    size_t row = (size_t)blockIdx.x * 64 + r;
    float* ol = g_Sl + row * CA;
    float* om = g_Sm + row * CA;
#pragma unroll
    for (int c2 = 0; c2 < 4; c2++) {
        float a0, a1, b0, b1, c0f, c1f, d0, d1;
        unpack2(al2[4 * c2 + 0], a0, a1);
        unpack2(al2[4 * c2 + 1], b0, b1);
        unpack2(al2[4 * c2 + 2], c0f, c1f);
        unpack2(al2[4 * c2 + 3], d0, d1);
        reinterpret_cast<float4*>(ol)[c2] = make_float4(a0 + a1, b0 + b1, c0f + c1f, d0 + d1);
        unpack2(am2[4 * c2 + 0], a0, a1);
        unpack2(am2[4 * c2 + 1], b0, b1);
        unpack2(am2[4 * c2 + 2], c0f, c1f);
        unpack2(am2[4 * c2 + 3], d0, d1);
        reinterpret_cast<float4*>(om)[c2] = make_float4(a0 + a1, b0 + b1, c0f + c1f, d0 + d1);
    }
}

// ---------------------------------------------------------------------------
// Kernel 0: pack per-atom metadata into one 16B record.
// ---------------------------------------------------------------------------
__global__ void pack_atoms_kernel(
    const float* __restrict__ is_motif_coord,
    const float* __restrict__ is_motif_seq,
    const int* __restrict__ ref_space_uid,
    const int* __restrict__ tok_idx)
{
    int i = blockIdx.x * blockDim.x + threadIdx.x;
    if (i >= LN) return;
    g_atom[i] = make_float4(is_motif_coord[i], is_motif_seq[i],
                            __int_as_float(ref_space_uid[i]),
                            __int_as_float(min(max(tok_idx[i], 0), IN - 1)));
}

// ---------------------------------------------------------------------------
// Kernel 3: pair assembly + residual MLP. Each thread handles TWO pairs
// (same lane k of two consecutive queries) so weight LDS is amortized 2x
// and two gather chains overlap.
// ---------------------------------------------------------------------------
__device__ __forceinline__ void mlp_layer2(const float* in, const ulonglong2* W2, float* out)
{
    u64 acc2[CA];
#pragma unroll
    for (int c = 0; c < CA; c++) acc2[c] = 0ull;
#pragma unroll
    for (int j2 = 0; j2 < 8; j2++) {
        u64 rr = pack2(fmaxf(in[2 * j2], 0.f), fmaxf(in[2 * j2 + 1], 0.f));
#pragma unroll
        for (int c2 = 0; c2 < 8; c2++) {
            ulonglong2 w = W2[j2 * 8 + c2];
            fma2(acc2[2 * c2], rr, w.x);
            fma2(acc2[2 * c2 + 1], rr, w.y);
        }
    }
#pragma unroll
    for (int c = 0; c < CA; c++) {
        float a, b;
        unpack2(acc2[c], a, b);
        out[c] = a + b;
    }
}

// one-pair MLP applied to two pairs with shared weight loads (4 fma2 / load)
__device__ __forceinline__ void mlp_layer2_x2(const float* in0, const float* in1,
                                              const ulonglong2* W2,
                                              float* out0, float* out1)
{
    u64 a0[CA], a1[CA];
#pragma unroll
    for (int c = 0; c < CA; c++) { a0[c] = 0ull; a1[c] = 0ull; }
#pragma unroll
    for (int j2 = 0; j2 < 8; j2++) {
        u64 r0 = pack2(fmaxf(in0[2 * j2], 0.f), fmaxf(in0[2 * j2 + 1], 0.f));
        u64 r1 = pack2(fmaxf(in1[2 * j2], 0.f), fmaxf(in1[2 * j2 + 1], 0.f));
#pragma unroll
        for (int c2 = 0; c2 < 8; c2++) {
            ulonglong2 w = W2[j2 * 8 + c2];
            fma2(a0[2 * c2], r0, w.x);
            fma2(a0[2 * c2 + 1], r0, w.y);
            fma2(a1[2 * c2], r1, w.x);
            fma2(a1[2 * c2 + 1], r1, w.y);
        }
    }
#pragma unroll
    for (int c = 0; c < CA; c++) {
        float a, b;
        unpack2(a0[c], a, b);
        out0[c] = a + b;
        unpack2(a1[c], a, b);
        out1[c] = a + b;
    }
}

struct PairCtx {
    const float* motif_pos;
    const float* ref_pos;
    const float* sWd_m; const float* sWi_m; const float* sWk_m;
    const float* sWd_r; const float* sWi_r; const float* sWk_r;
};

__device__ __forceinline__ void compute_P(const PairCtx& cx, int q, int lane,
                                          const int* __restrict__ indices,
                                          float* P)
{
    int b = q / LN;
    int l = q - b * LN;

    int idx = indices[(size_t)q * KN + lane];
    idx = min(max(idx, 0), LN - 1);

    float4 ka = __ldg(g_atom + idx);
    float4 qa = __ldg(g_atom + l);
    int tk = __float_as_int(ka.w);
    int tq = __float_as_int(qa.w);

    const float4* slp = reinterpret_cast<const float4*>(g_Sl + (size_t)q * CA);
    const float4* smp = reinterpret_cast<const float4*>(g_Sm + ((size_t)b * LN + idx) * CA);
    const float4* zp  = reinterpret_cast<const float4*>(g_Zp + ((size_t)tq * IN + tk) * CA);
#pragma unroll
    for (int cc = 0; cc < 4; cc++) {
        float4 a = __ldg(slp + cc);
        float4 m = __ldg(smp + cc);
        float4 z = __ldg(zp + cc);
        P[cc * 4 + 0] = a.x + m.x + z.x;
        P[cc * 4 + 1] = a.y + m.y + z.y;
        P[cc * 4 + 2] = a.z + m.z + z.z;
        P[cc * 4 + 3] = a.w + m.w + z.w;
    }

    if (qa.x != 0.f && ka.x != 0.f) {
        float dx = cx.motif_pos[l * 3 + 0] - cx.motif_pos[idx * 3 + 0];
        float dy = cx.motif_pos[l * 3 + 1] - cx.motif_pos[idx * 3 + 1];
        float dz = cx.motif_pos[l * 3 + 2] - cx.motif_pos[idx * 3 + 2];
        float inv = 1.0f / (1.0f + dx * dx + dy * dy + dz * dz);
#pragma unroll
        for (int c = 0; c < CA; c++)
            P[c] += dx * cx.sWd_m[c] + dy * cx.sWd_m[CA + c] + dz * cx.sWd_m[2 * CA + c]
                  + inv * cx.sWi_m[c] + cx.sWk_m[c];
    }

    if (qa.y != 0.f && __float_as_int(ka.z) == __float_as_int(qa.z) && ka.y != 0.f) {
        float dx = cx.ref_pos[l * 3 + 0] - cx.ref_pos[idx * 3 + 0];
        float dy = cx.ref_pos[l * 3 + 1] - cx.ref_pos[idx * 3 + 1];
        float dz = cx.ref_pos[l * 3 + 2] - cx.ref_pos[idx * 3 + 2];
        float inv = 1.0f / (1.0f + dx * dx + dy * dy + dz * dz);
#pragma unroll
        for (int c = 0; c < CA; c++)
            P[c] += dx * cx.sWd_r[c] + dy * cx.sWd_r[CA + c] + dz * cx.sWd_r[2 * CA + c]
                  + inv * cx.sWi_r[c] + cx.sWk_r[c];
    }
}

__global__ void __launch_bounds__(128) pair_kernel(
    const float* __restrict__ motif_pos,
    const float* __restrict__ ref_pos,
    const int* __restrict__ indices,
    const float* __restrict__ Wd_m, const float* __restrict__ Wi_m, const float* __restrict__ Wk_m,
    const float* __restrict__ Wd_r, const float* __restrict__ Wi_r, const float* __restrict__ Wk_r,
    const float* __restrict__ W1, const float* __restrict__ W2, const float* __restrict__ W3,
    float* __restrict__ out)
{
    __shared__ float sWd_m[3 * CA], sWi_m[CA], sWk_m[CA];
    __shared__ float sWd_r[3 * CA], sWi_r[CA], sWk_r[CA];
    __shared__ ulonglong2 sW1_2[64], sW2_2[64], sW3_2[64];

    int t = threadIdx.x;
    for (int i = t; i < 3 * CA; i += 128) { sWd_m[i] = Wd_m[i]; sWd_r[i] = Wd_r[i]; }
    for (int i = t; i < CA; i += 128) {
        sWi_m[i] = Wi_m[i]; sWk_m[i] = Wk_m[i];
        sWi_r[i] = Wi_r[i]; sWk_r[i] = Wk_r[i];
    }
    for (int i = t; i < 64; i += 128) {
        int j2 = i >> 3, c2 = i & 7;
        int j0 = 2 * j2, j1 = j0 + 1, c0 = 2 * c2, c1 = c0 + 1;
        sW1_2[i] = make_ulonglong2(pack2(W1[j0 * CA + c0], W1[j1 * CA + c0]),
                                   pack2(W1[j0 * CA + c1], W1[j1 * CA + c1]));
        sW2_2[i] = make_ulonglong2(pack2(W2[j0 * CA + c0], W2[j1 * CA + c0]),
                                   pack2(W2[j0 * CA + c1], W2[j1 * CA + c1]));
        sW3_2[i] = make_ulonglong2(pack2(W3[j0 * CA + c0], W3[j1 * CA + c0]),
                                   pack2(W3[j0 * CA + c1], W3[j1 * CA + c1]));
    }
    __syncthreads();

    int warp = blockIdx.x * 4 + (t >> 5);
    int q0 = warp * 2;                    // two queries per warp
    int q1 = q0 + 1;
    if (q1 >= BN * LN) return;
    int lane = t & 31;

    PairCtx cx{motif_pos, ref_pos, sWd_m, sWi_m, sWk_m, sWd_r, sWi_r, sWk_r};

    float P0[CA], P1[CA];
    compute_P(cx, q0, lane, indices, P0);
    compute_P(cx, q1, lane, indices, P1);

    float h0a[CA], h0b[CA], h1a[CA], h1b[CA];
    mlp_layer2_x2(P0,  P1,  sW1_2, h0a, h1a);
    mlp_layer2_x2(h0a, h1a, sW2_2, h0b, h1b);
    mlp_layer2_x2(h0b, h1b, sW3_2, h0a, h1a);

    float4* op0 = reinterpret_cast<float4*>(out + ((size_t)q0 * KN + lane) * CA);
    float4* op1 = reinterpret_cast<float4*>(out + ((size_t)q1 * KN + lane) * CA);
#pragma unroll
    for (int cc = 0; cc < 4; cc++) {
        op0[cc] = make_float4(P0[cc * 4 + 0] + h0a[cc * 4 + 0],
                              P0[cc * 4 + 1] + h0a[cc * 4 + 1],
                              P0[cc * 4 + 2] + h0a[cc * 4 + 2],
                              P0[cc * 4 + 3] + h0a[cc * 4 + 3]);
        op1[cc] = make_float4(P1[cc * 4 + 0] + h1a[cc * 4 + 0],
                              P1[cc * 4 + 1] + h1a[cc * 4 + 1],
                              P1[cc * 4 + 2] + h1a[cc * 4 + 2],
                              P1[cc * 4 + 3] + h1a[cc * 4 + 3]);
    }
}

// ---------------------------------------------------------------------------
extern "C" void kernel_launch(void* const* d_in, const int* in_sizes, int n_in,
                              void* d_out, int out_size)
{
    const float* motif_pos      = (const float*)d_in[0];
    const float* is_motif_coord = (const float*)d_in[1];
    const float* ref_pos        = (const float*)d_in[2];
    const int*   ref_space_uid  = (const int*)d_in[3];
    const float* is_motif_seq   = (const float*)d_in[4];
    const int*   indices        = (const int*)d_in[5];
    const float* C_L            = (const float*)d_in[6];
    const float* Z              = (const float*)d_in[7];
    const int*   tok_idx        = (const int*)d_in[8];
    const float* W_d_m          = (const float*)d_in[9];
    const float* W_inv_m        = (const float*)d_in[10];
    const float* W_mask_m       = (const float*)d_in[11];
    const float* W_d_r          = (const float*)d_in[12];
    const float* W_inv_r        = (const float*)d_in[13];
    const float* W_mask_r       = (const float*)d_in[14];
    const float* W_single_l     = (const float*)d_in[15];
    const float* W_single_m     = (const float*)d_in[16];
    const float* rms_w          = (const float*)d_in[17];
    const float* W_z            = (const float*)d_in[18];
    const float* W_mlp1         = (const float*)d_in[19];
    const float* W_mlp2         = (const float*)d_in[20];
    const float* W_mlp3         = (const float*)d_in[21];
    float* out = (float*)d_out;

    zproc_kernel<<<(IN * IN) / ZR2, 128>>>(Z, rms_w, W_z);
    pack_atoms_kernel<<<(LN + 127) / 128, 128>>>(is_motif_coord, is_motif_seq,
                                                 ref_space_uid, tok_idx);
    sproj_kernel<<<(BN * LN) / 64, 64>>>(C_L, W_single_l, W_single_m);
    // warp handles 2 queries; block = 4 warps = 8 queries
    pair_kernel<<<(BN * LN) / 8, 128>>>(
        motif_pos, ref_pos, indices,
        W_d_m, W_inv_m, W_mask_m, W_d_r, W_inv_r, W_mask_r,
        W_mlp1, W_mlp2, W_mlp3, out);
}

// round 7
// speedup vs baseline: 1.5299x; 1.0127x over previous
#include <cuda_runtime.h>

#define BN 2
#define LN 12288
#define KN 32
#define IN 768
#define CT 128
#define CA 16
#define RMS_EPS 1e-6f

typedef unsigned long long u64;

// Scratch (allocs are banned; device globals are the sanctioned workaround)
__device__ float g_Sl[BN * LN * CA];                  // 1.5 MB
__device__ float g_Sm[BN * LN * CA];                  // 1.5 MB
__device__ float g_Zp[(size_t)IN * IN * CA];          // 37.75 MB
__device__ float4 g_mp[LN];                           // motif pos + meta bits
__device__ float4 g_rp[LN];                           // ref pos

// ---- packed f32x2 helpers (sm_100+) ---------------------------------------
__device__ __forceinline__ u64 pack2(float a, float b) {
    u64 v;
    asm("mov.b64 %0, {%1, %2};" : "=l"(v) : "r"(__float_as_uint(a)), "r"(__float_as_uint(b)));
    return v;
}
__device__ __forceinline__ void unpack2(u64 v, float& a, float& b) {
    unsigned x, y;
    asm("mov.b64 {%0, %1}, %2;" : "=r"(x), "=r"(y) : "l"(v));
    a = __uint_as_float(x); b = __uint_as_float(y);
}
__device__ __forceinline__ void fma2(u64& d, u64 a, u64 b) {
    asm("fma.rn.f32x2 %0, %1, %2, %0;" : "+l"(d) : "l"(a), "l"(b));
}
__device__ __forceinline__ void cp_async16(void* smem_dst, const void* gmem_src) {
    unsigned s = (unsigned)__cvta_generic_to_shared(smem_dst);
    asm volatile("cp.async.cg.shared.global [%0], [%1], 16;\n" :: "r"(s), "l"(gmem_src));
}
__device__ __forceinline__ void cp_async_wait_all() {
    asm volatile("cp.async.commit_group;\ncp.async.wait_group 0;\n" ::: "memory");
}

// ---------------------------------------------------------------------------
// Kernel 2 (first, dominant): Z_proc = rmsnorm(Z)*rms_w @ W_z.
// 512 rows / 128-thread block, 4 rows per thread (r, r+128, r+256, r+384):
// each per-t weight load (4 LDS.128) feeds 4 rows. Accumulators are f32x2
// packed over the OUTPUT dim (acc[c2] = cols 2c2,2c2+1) -> 8 u64 per row.
// K staged in 8 chunks of 4 float4, pitch 5 float4 (20 words: conflict-free).
// ---------------------------------------------------------------------------
#define ZR3 512

__global__ void __launch_bounds__(128) zproc_kernel(
    const float* __restrict__ Z,
    const float* __restrict__ rmsw,
    const float* __restrict__ Wz)
{
    __shared__ float4 sX[ZR3 * 5];                     // 40960 B
    __shared__ ulonglong2 sW[CT * 2];                  // 8192 B: per t, 2 ulonglong2x2
    // layout: sW[t*2 + p] = { pack2(W[t][8p+0],W[t][8p+1]), pack2(W[t][8p+2],W[t][8p+3]) }
    // and sWb[t*2+p] second half handled by indexing: we store 4 ulonglong2 per t
    // -> use flat array of 4 per t:
    __shared__ ulonglong2 sW2[CT * 2];                 // second 8 cols (8..15)

    for (int i = threadIdx.x; i < CT * 2; i += 128) {
        int t = i >> 1, p = i & 1;                     // p: col group (0-3 / 4-7)
        float rw = rmsw[t];
        const float* w = Wz + t * CA;
        sW [i] = make_ulonglong2(pack2(rw * w[4 * p + 0], rw * w[4 * p + 1]),
                                 pack2(rw * w[4 * p + 2], rw * w[4 * p + 3]));
        sW2[i] = make_ulonglong2(pack2(rw * w[8 + 4 * p + 0], rw * w[8 + 4 * p + 1]),
                                 pack2(rw * w[8 + 4 * p + 2], rw * w[8 + 4 * p + 3]));
    }

    int r = threadIdx.x;
    const float4* src = reinterpret_cast<const float4*>(Z) + (size_t)blockIdx.x * ZR3 * 32;

    u64 acc[4][8];
#pragma unroll
    for (int k = 0; k < 4; k++)
#pragma unroll
        for (int c = 0; c < 8; c++) acc[k][c] = 0ull;
    float ss[4] = {0.f, 0.f, 0.f, 0.f};

#pragma unroll 1
    for (int h = 0; h < 8; h++) {
        __syncthreads();
        // stage chunk h: 512 rows x 4 float4 (64B runs)
#pragma unroll 4
        for (int j = threadIdx.x; j < ZR3 * 4; j += 128) {
            int row = j >> 2, col = j & 3;
            cp_async16(&sX[row * 5 + col], src + row * 32 + h * 4 + col);
        }
        cp_async_wait_all();
        __syncthreads();

#pragma unroll
        for (int i = 0; i < 4; i++) {
            float4 v0 = sX[(r      ) * 5 + i];
            float4 v1 = sX[(r + 128) * 5 + i];
            float4 v2 = sX[(r + 256) * 5 + i];
            float4 v3 = sX[(r + 384) * 5 + i];
            float x0[4] = {v0.x, v0.y, v0.z, v0.w};
            float x1[4] = {v1.x, v1.y, v1.z, v1.w};
            float x2[4] = {v2.x, v2.y, v2.z, v2.w};
            float x3[4] = {v3.x, v3.y, v3.z, v3.w};
            int tb = (h * 4 + i) * 4;
#pragma unroll
            for (int e = 0; e < 4; e++) {
                int t = tb + e;
                ulonglong2 wA = sW [t * 2 + 0];        // cols 0-3
                ulonglong2 wB = sW [t * 2 + 1];        // cols 4-7
                ulonglong2 wC = sW2[t * 2 + 0];        // cols 8-11
                ulonglong2 wD = sW2[t * 2 + 1];        // cols 12-15
                u64 b0 = pack2(x0[e], x0[e]);
                u64 b1 = pack2(x1[e], x1[e]);
                u64 b2 = pack2(x2[e], x2[e]);
                u64 b3 = pack2(x3[e], x3[e]);
                fma2(acc[0][0], b0, wA.x); fma2(acc[0][1], b0, wA.y);
                fma2(acc[0][2], b0, wB.x); fma2(acc[0][3], b0, wB.y);
                fma2(acc[0][4], b0, wC.x); fma2(acc[0][5], b0, wC.y);
                fma2(acc[0][6], b0, wD.x); fma2(acc[0][7], b0, wD.y);
                fma2(acc[1][0], b1, wA.x); fma2(acc[1][1], b1, wA.y);
                fma2(acc[1][2], b1, wB.x); fma2(acc[1][3], b1, wB.y);
                fma2(acc[1][4], b1, wC.x); fma2(acc[1][5], b1, wC.y);
                fma2(acc[1][6], b1, wD.x); fma2(acc[1][7], b1, wD.y);
                fma2(acc[2][0], b2, wA.x); fma2(acc[2][1], b2, wA.y);
                fma2(acc[2][2], b2, wB.x); fma2(acc[2][3], b2, wB.y);
                fma2(acc[2][4], b2, wC.x); fma2(acc[2][5], b2, wC.y);
                fma2(acc[2][6], b2, wD.x); fma2(acc[2][7], b2, wD.y);
                fma2(acc[3][0], b3, wA.x); fma2(acc[3][1], b3, wA.y);
                fma2(acc[3][2], b3, wB.x); fma2(acc[3][3], b3, wB.y);
                fma2(acc[3][4], b3, wC.x); fma2(acc[3][5], b3, wC.y);
                fma2(acc[3][6], b3, wD.x); fma2(acc[3][7], b3, wD.y);
                ss[0] = fmaf(x0[e], x0[e], ss[0]);
                ss[1] = fmaf(x1[e], x1[e], ss[1]);
                ss[2] = fmaf(x2[e], x2[e], ss[2]);
                ss[3] = fmaf(x3[e], x3[e], ss[3]);
            }
        }
    }

#pragma unroll
    for (int k = 0; k < 4; k++) {
        float scale = rsqrtf(ss[k] * (1.0f / CT) + RMS_EPS);
        float* o = g_Zp + ((size_t)blockIdx.x * ZR3 + r + 128 * k) * CA;
#pragma unroll
        for (int c4 = 0; c4 < 4; c4++) {
            float a0, a1, b0, b1;
            unpack2(acc[k][2 * c4 + 0], a0, a1);
            unpack2(acc[k][2 * c4 + 1], b0, b1);
            reinterpret_cast<float4*>(o)[c4] =
                make_float4(a0 * scale, a1 * scale, b0 * scale, b1 * scale);
        }
    }
}

// ---------------------------------------------------------------------------
// Kernel 1: S_l / S_m projections (unchanged from R6).
// ---------------------------------------------------------------------------
__global__ void __launch_bounds__(64) sproj_kernel(
    const float* __restrict__ CL,
    const float* __restrict__ Wl,
    const float* __restrict__ Wm)
{
    __shared__ float sX[64 * 68];
    __shared__ ulonglong2 sWl2[512];
    __shared__ ulonglong2 sWm2[512];

    for (int i = threadIdx.x; i < 512; i += 64) {
        int t2 = i >> 3, c2 = i & 7;
        int t0 = 2 * t2, t1 = t0 + 1, c0 = 2 * c2, c1 = c0 + 1;
        sWl2[i] = make_ulonglong2(pack2(Wl[t0 * CA + c0], Wl[t1 * CA + c0]),
                                  pack2(Wl[t0 * CA + c1], Wl[t1 * CA + c1]));
        sWm2[i] = make_ulonglong2(pack2(Wm[t0 * CA + c0], Wm[t1 * CA + c0]),
                                  pack2(Wm[t0 * CA + c1], Wm[t1 * CA + c1]));
    }

    int r = threadIdx.x;
    u64 al2[CA], am2[CA];
#pragma unroll
    for (int c = 0; c < CA; c++) { al2[c] = 0ull; am2[c] = 0ull; }

    const float4* src = reinterpret_cast<const float4*>(CL + (size_t)blockIdx.x * 64 * CT);

#pragma unroll 1
    for (int h = 0; h < 2; h++) {
        __syncthreads();
#pragma unroll 4
        for (int j = threadIdx.x; j < 64 * 16; j += 64) {
            int row = j >> 4, col = j & 15;
            cp_async16(&reinterpret_cast<float4*>(sX)[row * 17 + col],
                       src + row * 32 + h * 16 + col);
        }
        cp_async_wait_all();
        __syncthreads();

        const float4* xr = reinterpret_cast<const float4*>(sX) + r * 17;
#pragma unroll 4
        for (int i = 0; i < 16; i++) {
            float4 v = xr[i];
            u64 p01 = pack2(fmaxf(v.x, 0.f), fmaxf(v.y, 0.f));
            u64 p23 = pack2(fmaxf(v.z, 0.f), fmaxf(v.w, 0.f));
            int t = h * 16 + i;
            const ulonglong2* wla = sWl2 + (2 * t) * 8;
            const ulonglong2* wlb = sWl2 + (2 * t + 1) * 8;
            const ulonglong2* wma = sWm2 + (2 * t) * 8;
            const ulonglong2* wmb = sWm2 + (2 * t + 1) * 8;
#pragma unroll
            for (int c2 = 0; c2 < 8; c2++) {
                ulonglong2 w = wla[c2];
                fma2(al2[2 * c2], p01, w.x);
                fma2(al2[2 * c2 + 1], p01, w.y);
            }
#pragma unroll
            for (int c2 = 0; c2 < 8; c2++) {
                ulonglong2 w = wlb[c2];
                fma2(al2[2 * c2], p23, w.x);
                fma2(al2[2 * c2 + 1], p23, w.y);
            }
#pragma unroll
            for (int c2 = 0; c2 < 8; c2++) {
                ulonglong2 w = wma[c2];
                fma2(am2[2 * c2], p01, w.x);
                fma2(am2[2 * c2 + 1], p01, w.y);
            }
#pragma unroll
            for (int c2 = 0; c2 < 8; c2++) {
                ulonglong2 w = wmb[c2];
                fma2(am2[2 * c2], p23, w.x);
                fma2(am2[2 * c2 + 1], p23, w.y);
            }
        }
    }

    size_t row = (size_t)blockIdx.x * 64 + r;
    float* ol = g_Sl + row * CA;
    float* om = g_Sm + row * CA;
#pragma unroll
    for (int c2 = 0; c2 < 4; c2++) {
        float a0, a1, b0, b1, c0f, c1f, d0, d1;
        unpack2(al2[4 * c2 + 0], a0, a1);
        unpack2(al2[4 * c2 + 1], b0, b1);
        unpack2(al2[4 * c2 + 2], c0f, c1f);
        unpack2(al2[4 * c2 + 3], d0, d1);
        reinterpret_cast<float4*>(ol)[c2] = make_float4(a0 + a1, b0 + b1, c0f + c1f, d0 + d1);
        unpack2(am2[4 * c2 + 0], a0, a1);
        unpack2(am2[4 * c2 + 1], b0, b1);
        unpack2(am2[4 * c2 + 2], c0f, c1f);
        unpack2(am2[4 * c2 + 3], d0, d1);
        reinterpret_cast<float4*>(om)[c2] = make_float4(a0 + a1, b0 + b1, c0f + c1f, d0 + d1);
    }
}

// ---------------------------------------------------------------------------
// Kernel 0: pack geometry + metadata tables.
// meta bits: uid[0:10) | seq<<10 | tok[11:21) | coord<<21
// ---------------------------------------------------------------------------
__global__ void pack_tables_kernel(
    const float* __restrict__ motif_pos,
    const float* __restrict__ ref_pos,
    const float* __restrict__ is_motif_coord,
    const float* __restrict__ is_motif_seq,
    const int* __restrict__ ref_space_uid,
    const int* __restrict__ tok_idx)
{
    int i = blockIdx.x * blockDim.x + threadIdx.x;
    if (i >= LN) return;
    int uid = ref_space_uid[i] & 1023;
    int seq = (is_motif_seq[i] != 0.f) ? 1 : 0;
    int tok = min(max(tok_idx[i], 0), IN - 1);
    int coord = (is_motif_coord[i] != 0.f) ? 1 : 0;
    int meta = uid | (seq << 10) | (tok << 11) | (coord << 21);
    g_mp[i] = make_float4(motif_pos[i * 3 + 0], motif_pos[i * 3 + 1],
                          motif_pos[i * 3 + 2], __int_as_float(meta));
    g_rp[i] = make_float4(ref_pos[i * 3 + 0], ref_pos[i * 3 + 1],
                          ref_pos[i * 3 + 2], 0.f);
}

// ---------------------------------------------------------------------------
// Kernel 3: pair assembly + residual MLP (2 queries per thread).
// ---------------------------------------------------------------------------
__device__ __forceinline__ void mlp_layer2_x2(const float* in0, const float* in1,
                                              const ulonglong2* W2,
                                              float* out0, float* out1)
{
    u64 a0[CA], a1[CA];
#pragma unroll
    for (int c = 0; c < CA; c++) { a0[c] = 0ull; a1[c] = 0ull; }
#pragma unroll
    for (int j2 = 0; j2 < 8; j2++) {
        u64 r0 = pack2(fmaxf(in0[2 * j2], 0.f), fmaxf(in0[2 * j2 + 1], 0.f));
        u64 r1 = pack2(fmaxf(in1[2 * j2], 0.f), fmaxf(in1[2 * j2 + 1], 0.f));
#pragma unroll
        for (int c2 = 0; c2 < 8; c2++) {
            ulonglong2 w = W2[j2 * 8 + c2];
            fma2(a0[2 * c2], r0, w.x);
            fma2(a0[2 * c2 + 1], r0, w.y);
            fma2(a1[2 * c2], r1, w.x);
            fma2(a1[2 * c2 + 1], r1, w.y);
        }
    }
#pragma unroll
    for (int c = 0; c < CA; c++) {
        float a, b;
        unpack2(a0[c], a, b);
        out0[c] = a + b;
        unpack2(a1[c], a, b);
        out1[c] = a + b;
    }
}

struct PairW {
    const float* sWd_m; const float* sWi_m; const float* sWk_m;
    const float* sWd_r; const float* sWi_r; const float* sWk_r;
};

__device__ __forceinline__ void compute_P(const PairW& cw, int q, int lane,
                                          const int* __restrict__ indices,
                                          float* P)
{
    int b = q / LN;
    int l = q - b * LN;

    int idx = indices[(size_t)q * KN + lane];
    idx = min(max(idx, 0), LN - 1);

    float4 mpk = __ldg(g_mp + idx);          // key pos+meta (1 scattered LDG.128)
    float4 mpq = __ldg(g_mp + l);            // query (warp-uniform)
    int mk = __float_as_int(mpk.w);
    int mq = __float_as_int(mpq.w);
    int tk = (mk >> 11) & 1023;
    int tq = (mq >> 11) & 1023;

    const float4* slp = reinterpret_cast<const float4*>(g_Sl + (size_t)q * CA);
    const float4* smp = reinterpret_cast<const float4*>(g_Sm + ((size_t)b * LN + idx) * CA);
    const float4* zp  = reinterpret_cast<const float4*>(g_Zp + ((size_t)tq * IN + tk) * CA);
#pragma unroll
    for (int cc = 0; cc < 4; cc++) {
        float4 a = __ldg(slp + cc);
        float4 m = __ldg(smp + cc);
        float4 z = __ldg(zp + cc);
        P[cc * 4 + 0] = a.x + m.x + z.x;
        P[cc * 4 + 1] = a.y + m.y + z.y;
        P[cc * 4 + 2] = a.z + m.z + z.z;
        P[cc * 4 + 3] = a.w + m.w + z.w;
    }

    int both = mk & mq;
    // motif branch: coord bit on both sides
    if ((both >> 21) & 1) {
        float dx = mpq.x - mpk.x;
        float dy = mpq.y - mpk.y;
        float dz = mpq.z - mpk.z;
        float inv = 1.0f / (1.0f + dx * dx + dy * dy + dz * dz);
#pragma unroll
        for (int c = 0; c < CA; c++)
            P[c] += dx * cw.sWd_m[c] + dy * cw.sWd_m[CA + c] + dz * cw.sWd_m[2 * CA + c]
                  + inv * cw.sWi_m[c] + cw.sWk_m[c];
    }

    // ref branch: seq bit on both sides AND same uid
    if (((both >> 10) & 1) && (((mk ^ mq) & 1023) == 0)) {
        float4 rpk = __ldg(g_rp + idx);
        float4 rpq = __ldg(g_rp + l);
        float dx = rpq.x - rpk.x;
        float dy = rpq.y - rpk.y;
        float dz = rpq.z - rpk.z;
        float inv = 1.0f / (1.0f + dx * dx + dy * dy + dz * dz);
#pragma unroll
        for (int c = 0; c < CA; c++)
            P[c] += dx * cw.sWd_r[c] + dy * cw.sWd_r[CA + c] + dz * cw.sWd_r[2 * CA + c]
                  + inv * cw.sWi_r[c] + cw.sWk_r[c];
    }
}

__global__ void __launch_bounds__(128) pair_kernel(
    const int* __restrict__ indices,
    const float* __restrict__ Wd_m, const float* __restrict__ Wi_m, const float* __restrict__ Wk_m,
    const float* __restrict__ Wd_r, const float* __restrict__ Wi_r, const float* __restrict__ Wk_r,
    const float* __restrict__ W1, const float* __restrict__ W2, const float* __restrict__ W3,
    float* __restrict__ out)
{
    __shared__ float sWd_m[3 * CA], sWi_m[CA], sWk_m[CA];
    __shared__ float sWd_r[3 * CA], sWi_r[CA], sWk_r[CA];
    __shared__ ulonglong2 sW1_2[64], sW2_2[64], sW3_2[64];

    int t = threadIdx.x;
    for (int i = t; i < 3 * CA; i += 128) { sWd_m[i] = Wd_m[i]; sWd_r[i] = Wd_r[i]; }
    for (int i = t; i < CA; i += 128) {
        sWi_m[i] = Wi_m[i]; sWk_m[i] = Wk_m[i];
        sWi_r[i] = Wi_r[i]; sWk_r[i] = Wk_r[i];
    }
    for (int i = t; i < 64; i += 128) {
        int j2 = i >> 3, c2 = i & 7;
        int j0 = 2 * j2, j1 = j0 + 1, c0 = 2 * c2, c1 = c0 + 1;
        sW1_2[i] = make_ulonglong2(pack2(W1[j0 * CA + c0], W1[j1 * CA + c0]),
                                   pack2(W1[j0 * CA + c1], W1[j1 * CA + c1]));
        sW2_2[i] = make_ulonglong2(pack2(W2[j0 * CA + c0], W2[j1 * CA + c0]),
                                   pack2(W2[j0 * CA + c1], W2[j1 * CA + c1]));
        sW3_2[i] = make_ulonglong2(pack2(W3[j0 * CA + c0], W3[j1 * CA + c0]),
                                   pack2(W3[j0 * CA + c1], W3[j1 * CA + c1]));
    }
    __syncthreads();

    int warp = blockIdx.x * 4 + (t >> 5);
    int q0 = warp * 2;
    int q1 = q0 + 1;
    if (q1 >= BN * LN) return;
    int lane = t & 31;

    PairW cw{sWd_m, sWi_m, sWk_m, sWd_r, sWi_r, sWk_r};

    float P0[CA], P1[CA];
    compute_P(cw, q0, lane, indices, P0);
    compute_P(cw, q1, lane, indices, P1);

    float h0a[CA], h0b[CA], h1a[CA], h1b[CA];
    mlp_layer2_x2(P0,  P1,  sW1_2, h0a, h1a);
    mlp_layer2_x2(h0a, h1a, sW2_2, h0b, h1b);
    mlp_layer2_x2(h0b, h1b, sW3_2, h0a, h1a);

    float4* op0 = reinterpret_cast<float4*>(out + ((size_t)q0 * KN + lane) * CA);
    float4* op1 = reinterpret_cast<float4*>(out + ((size_t)q1 * KN + lane) * CA);
#pragma unroll
    for (int cc = 0; cc < 4; cc++) {
        op0[cc] = make_float4(P0[cc * 4 + 0] + h0a[cc * 4 + 0],
                              P0[cc * 4 + 1] + h0a[cc * 4 + 1],
                              P0[cc * 4 + 2] + h0a[cc * 4 + 2],
                              P0[cc * 4 + 3] + h0a[cc * 4 + 3]);
        op1[cc] = make_float4(P1[cc * 4 + 0] + h1a[cc * 4 + 0],
                              P1[cc * 4 + 1] + h1a[cc * 4 + 1],
                              P1[cc * 4 + 2] + h1a[cc * 4 + 2],
                              P1[cc * 4 + 3] + h1a[cc * 4 + 3]);
    }
}

// ---------------------------------------------------------------------------
extern "C" void kernel_launch(void* const* d_in, const int* in_sizes, int n_in,
                              void* d_out, int out_size)
{
    const float* motif_pos      = (const float*)d_in[0];
    const float* is_motif_coord = (const float*)d_in[1];
    const float* ref_pos        = (const float*)d_in[2];
    const int*   ref_space_uid  = (const int*)d_in[3];
    const float* is_motif_seq   = (const float*)d_in[4];
    const int*   indices        = (const int*)d_in[5];
    const float* C_L            = (const float*)d_in[6];
    const float* Z              = (const float*)d_in[7];
    const int*   tok_idx        = (const int*)d_in[8];
    const float* W_d_m          = (const float*)d_in[9];
    const float* W_inv_m        = (const float*)d_in[10];
    const float* W_mask_m       = (const float*)d_in[11];
    const float* W_d_r          = (const float*)d_in[12];
    const float* W_inv_r        = (const float*)d_in[13];
    const float* W_mask_r       = (const float*)d_in[14];
    const float* W_single_l     = (const float*)d_in[15];
    const float* W_single_m     = (const float*)d_in[16];
    const float* rms_w          = (const float*)d_in[17];
    const float* W_z            = (const float*)d_in[18];
    const float* W_mlp1         = (const float*)d_in[19];
    const float* W_mlp2         = (const float*)d_in[20];
    const float* W_mlp3         = (const float*)d_in[21];
    float* out = (float*)d_out;

    zproc_kernel<<<(IN * IN) / ZR3, 128>>>(Z, rms_w, W_z);
    pack_tables_kernel<<<(LN + 127) / 128, 128>>>(motif_pos, ref_pos,
                                                  is_motif_coord, is_motif_seq,
                                                  ref_space_uid, tok_idx);
    sproj_kernel<<<(BN * LN) / 64, 64>>>(C_L, W_single_l, W_single_m);
    pair_kernel<<<(BN * LN) / 8, 128>>>(
        indices,
        W_d_m, W_inv_m, W_mask_m, W_d_r, W_inv_r, W_mask_r,
        W_mlp1, W_mlp2, W_mlp3, out);
}